// round 1
// baseline (speedup 1.0000x reference)
#include <cuda_runtime.h>
#include <math.h>

#define BB 2
#define LL 2048
#define DD 1024
#define HH 16
#define HDIM 64
#define HIDD 4096
#define NROWS (BB*LL)   // 4096

// ---------------- scratch (static device globals; no allocation) ----------------
__device__ float g_ln1 [NROWS*DD];
__device__ float g_q   [NROWS*DD];
__device__ float g_k   [NROWS*DD];
__device__ float g_v   [NROWS*DD];
__device__ float g_attn[NROWS*DD];
__device__ float g_h   [NROWS*DD];
__device__ float g_ln2 [NROWS*DD];
__device__ float g_gate[(size_t)NROWS*HIDD];
__device__ float g_f   [(size_t)NROWS*HIDD];

// ---------------- LayerNorm: one block per row of 1024 ----------------
__global__ __launch_bounds__(256) void ln_kernel(const float* __restrict__ x,
                                                 const float* __restrict__ gamma,
                                                 const float* __restrict__ beta,
                                                 float* __restrict__ y)
{
    const int row = blockIdx.x;
    const int tid = threadIdx.x;
    const float4 v = reinterpret_cast<const float4*>(x + (size_t)row * DD)[tid];
    float s = v.x + v.y + v.z + v.w;
    float q = v.x*v.x + v.y*v.y + v.z*v.z + v.w*v.w;
    #pragma unroll
    for (int o = 16; o >= 1; o >>= 1) {
        s += __shfl_xor_sync(0xffffffffu, s, o);
        q += __shfl_xor_sync(0xffffffffu, q, o);
    }
    __shared__ float ss[8], sq[8];
    __shared__ float stats[2];
    const int wid = tid >> 5;
    if ((tid & 31) == 0) { ss[wid] = s; sq[wid] = q; }
    __syncthreads();
    if (tid == 0) {
        float ts = 0.f, tq = 0.f;
        #pragma unroll
        for (int i = 0; i < 8; i++) { ts += ss[i]; tq += sq[i]; }
        float mu  = ts * (1.0f / DD);
        float var = tq * (1.0f / DD) - mu * mu;
        stats[0] = mu;
        stats[1] = rsqrtf(var + 1e-5f);
    }
    __syncthreads();
    const float mu = stats[0], rs = stats[1];
    const float4 g4 = reinterpret_cast<const float4*>(gamma)[tid];
    const float4 b4 = reinterpret_cast<const float4*>(beta)[tid];
    float4 o;
    o.x = (v.x - mu) * rs * g4.x + b4.x;
    o.y = (v.y - mu) * rs * g4.y + b4.y;
    o.z = (v.z - mu) * rs * g4.z + b4.z;
    o.w = (v.w - mu) * rs * g4.w + b4.w;
    reinterpret_cast<float4*>(y + (size_t)row * DD)[tid] = o;
}

// ---------------- SGEMM (NT): C[M,N] = A[M,K] @ W[N,K]^T, fused epilogues ----------------
// modes
#define EP_NONE     0
#define EP_RES      1   // C = acc + res
#define EP_SILU_MUL 2   // C = silu(acc + bias[col]) * mul
#define EP_BIAS_RES 3   // C = acc + bias[col] + res

__global__ __launch_bounds__(256) void sgemm_nt(
    const float* __restrict__ A, const float* __restrict__ W,
    float* __restrict__ C, int M, int N, int K,
    const float* __restrict__ bias, const float* __restrict__ res,
    const float* __restrict__ mul, int mode)
{
    __shared__ float As[8][128];
    __shared__ float Bs[8][128];

    const int tid  = threadIdx.x;
    const int row0 = blockIdx.y * 128;
    const int col0 = blockIdx.x * 128;
    const int ty = tid >> 4, tx = tid & 15;
    const int lr = tid >> 1;           // 0..127
    const int lc = (tid & 1) << 2;     // 0 or 4

    const float* Ap = A + (size_t)(row0 + lr) * K + lc;
    const float* Wp = W + (size_t)(col0 + lr) * K + lc;

    float acc[8][8];
    #pragma unroll
    for (int i = 0; i < 8; i++)
        #pragma unroll
        for (int j = 0; j < 8; j++) acc[i][j] = 0.f;

    for (int kt = 0; kt < K; kt += 8) {
        const float4 av = *reinterpret_cast<const float4*>(Ap + kt);
        const float4 wv = *reinterpret_cast<const float4*>(Wp + kt);
        As[lc + 0][lr] = av.x; As[lc + 1][lr] = av.y;
        As[lc + 2][lr] = av.z; As[lc + 3][lr] = av.w;
        Bs[lc + 0][lr] = wv.x; Bs[lc + 1][lr] = wv.y;
        Bs[lc + 2][lr] = wv.z; Bs[lc + 3][lr] = wv.w;
        __syncthreads();
        #pragma unroll
        for (int k = 0; k < 8; k++) {
            const float4 a0 = *reinterpret_cast<const float4*>(&As[k][ty * 8]);
            const float4 a1 = *reinterpret_cast<const float4*>(&As[k][ty * 8 + 4]);
            const float4 b0 = *reinterpret_cast<const float4*>(&Bs[k][tx * 8]);
            const float4 b1 = *reinterpret_cast<const float4*>(&Bs[k][tx * 8 + 4]);
            const float a[8] = {a0.x, a0.y, a0.z, a0.w, a1.x, a1.y, a1.z, a1.w};
            const float b[8] = {b0.x, b0.y, b0.z, b0.w, b1.x, b1.y, b1.z, b1.w};
            #pragma unroll
            for (int i = 0; i < 8; i++)
                #pragma unroll
                for (int j = 0; j < 8; j++)
                    acc[i][j] = fmaf(a[i], b[j], acc[i][j]);
        }
        __syncthreads();
    }

    #pragma unroll
    for (int i = 0; i < 8; i++) {
        const int r = row0 + ty * 8 + i;
        const int c = col0 + tx * 8;
        const size_t idx = (size_t)r * N + c;
        float o[8];
        #pragma unroll
        for (int j = 0; j < 8; j++) o[j] = acc[i][j];

        if (mode == EP_RES) {
            const float4 r0v = *reinterpret_cast<const float4*>(&res[idx]);
            const float4 r1v = *reinterpret_cast<const float4*>(&res[idx + 4]);
            o[0] += r0v.x; o[1] += r0v.y; o[2] += r0v.z; o[3] += r0v.w;
            o[4] += r1v.x; o[5] += r1v.y; o[6] += r1v.z; o[7] += r1v.w;
        } else if (mode == EP_SILU_MUL) {
            const float4 bi0 = *reinterpret_cast<const float4*>(&bias[c]);
            const float4 bi1 = *reinterpret_cast<const float4*>(&bias[c + 4]);
            const float4 m0  = *reinterpret_cast<const float4*>(&mul[idx]);
            const float4 m1  = *reinterpret_cast<const float4*>(&mul[idx + 4]);
            const float bb[8] = {bi0.x, bi0.y, bi0.z, bi0.w, bi1.x, bi1.y, bi1.z, bi1.w};
            const float mm[8] = {m0.x, m0.y, m0.z, m0.w, m1.x, m1.y, m1.z, m1.w};
            #pragma unroll
            for (int j = 0; j < 8; j++) {
                const float vv = o[j] + bb[j];
                o[j] = vv / (1.f + __expf(-vv)) * mm[j];
            }
        } else if (mode == EP_BIAS_RES) {
            const float4 bi0 = *reinterpret_cast<const float4*>(&bias[c]);
            const float4 bi1 = *reinterpret_cast<const float4*>(&bias[c + 4]);
            const float4 r0v = *reinterpret_cast<const float4*>(&res[idx]);
            const float4 r1v = *reinterpret_cast<const float4*>(&res[idx + 4]);
            o[0] += bi0.x + r0v.x; o[1] += bi0.y + r0v.y;
            o[2] += bi0.z + r0v.z; o[3] += bi0.w + r0v.w;
            o[4] += bi1.x + r1v.x; o[5] += bi1.y + r1v.y;
            o[6] += bi1.z + r1v.z; o[7] += bi1.w + r1v.w;
        }
        *reinterpret_cast<float4*>(&C[idx])     = make_float4(o[0], o[1], o[2], o[3]);
        *reinterpret_cast<float4*>(&C[idx + 4]) = make_float4(o[4], o[5], o[6], o[7]);
    }
}

// ---------------- Causal flash attention, BQ=BK=64, HD=64 ----------------
// Q,K,V layout: [B, L, H, HD] contiguous as [(b*L+l)*1024 + h*64 + d]
#define ATTN_SMEM_FLOATS (64*64 + 64*64 + 64*65 + 64*65)

__global__ __launch_bounds__(256) void attn_kernel(
    const float* __restrict__ Q, const float* __restrict__ Kx,
    const float* __restrict__ V, float* __restrict__ O)
{
    extern __shared__ float sm[];
    float* Qs = sm;               // [64][64]
    float* Ps = Qs + 64 * 64;     // [64][64]
    float* Ks = Ps + 64 * 64;     // [64][65]
    float* Vs = Ks + 64 * 65;     // [64][65]

    const int tid = threadIdx.x;
    const int qt  = blockIdx.x;           // query tile (64 rows)
    const int bh  = blockIdx.y;
    const int b   = bh >> 4, h = bh & 15;
    const int ty  = tid >> 4, tx = tid & 15;
    const int r0  = ty * 4, c0 = tx * 4;

    const size_t base = ((size_t)b * LL) * DD + (size_t)h * HDIM;
    const float* qg = Q + base + (size_t)(qt * 64) * DD;

    for (int e = tid; e < 64 * 16; e += 256) {
        const int r = e >> 4, c4 = (e & 15) << 2;
        const float4 v = *reinterpret_cast<const float4*>(qg + (size_t)r * DD + c4);
        *reinterpret_cast<float4*>(&Qs[r * 64 + c4]) = v;
    }

    float o[4][4];
    float m[4], l[4];
    #pragma unroll
    for (int i = 0; i < 4; i++) {
        m[i] = -1e30f; l[i] = 0.f;
        #pragma unroll
        for (int j = 0; j < 4; j++) o[i][j] = 0.f;
    }

    for (int kt = 0; kt <= qt; kt++) {
        const float* kg = Kx + base + (size_t)(kt * 64) * DD;
        const float* vg = V  + base + (size_t)(kt * 64) * DD;
        __syncthreads();   // covers Qs first iter; protects Ks/Vs/Ps from prior readers
        for (int e = tid; e < 64 * 16; e += 256) {
            const int r = e >> 4, c4 = (e & 15) << 2;
            const float4 kv = *reinterpret_cast<const float4*>(kg + (size_t)r * DD + c4);
            const float4 vv = *reinterpret_cast<const float4*>(vg + (size_t)r * DD + c4);
            Ks[r * 65 + c4 + 0] = kv.x; Ks[r * 65 + c4 + 1] = kv.y;
            Ks[r * 65 + c4 + 2] = kv.z; Ks[r * 65 + c4 + 3] = kv.w;
            Vs[r * 65 + c4 + 0] = vv.x; Vs[r * 65 + c4 + 1] = vv.y;
            Vs[r * 65 + c4 + 2] = vv.z; Vs[r * 65 + c4 + 3] = vv.w;
        }
        __syncthreads();

        float s[4][4];
        #pragma unroll
        for (int i = 0; i < 4; i++)
            #pragma unroll
            for (int j = 0; j < 4; j++) s[i][j] = 0.f;

        #pragma unroll 4
        for (int d = 0; d < 64; d++) {
            const float a0 = Qs[(r0 + 0) * 64 + d];
            const float a1 = Qs[(r0 + 1) * 64 + d];
            const float a2 = Qs[(r0 + 2) * 64 + d];
            const float a3 = Qs[(r0 + 3) * 64 + d];
            const float b0 = Ks[(c0 + 0) * 65 + d];
            const float b1 = Ks[(c0 + 1) * 65 + d];
            const float b2 = Ks[(c0 + 2) * 65 + d];
            const float b3 = Ks[(c0 + 3) * 65 + d];
            s[0][0] = fmaf(a0, b0, s[0][0]); s[0][1] = fmaf(a0, b1, s[0][1]);
            s[0][2] = fmaf(a0, b2, s[0][2]); s[0][3] = fmaf(a0, b3, s[0][3]);
            s[1][0] = fmaf(a1, b0, s[1][0]); s[1][1] = fmaf(a1, b1, s[1][1]);
            s[1][2] = fmaf(a1, b2, s[1][2]); s[1][3] = fmaf(a1, b3, s[1][3]);
            s[2][0] = fmaf(a2, b0, s[2][0]); s[2][1] = fmaf(a2, b1, s[2][1]);
            s[2][2] = fmaf(a2, b2, s[2][2]); s[2][3] = fmaf(a2, b3, s[2][3]);
            s[3][0] = fmaf(a3, b0, s[3][0]); s[3][1] = fmaf(a3, b1, s[3][1]);
            s[3][2] = fmaf(a3, b2, s[3][2]); s[3][3] = fmaf(a3, b3, s[3][3]);
        }

        // scale + additive key position bias + causal mask
        #pragma unroll
        for (int i = 0; i < 4; i++)
            #pragma unroll
            for (int j = 0; j < 4; j++) {
                float val = s[i][j] * 0.125f + 0.01f * (float)(kt * 64 + c0 + j);
                if (kt == qt && (c0 + j) > (r0 + i)) val = -1e30f;
                s[i][j] = val;
            }

        // online softmax (row stats reduced across the 16 tx lanes)
        #pragma unroll
        for (int i = 0; i < 4; i++) {
            float mx = fmaxf(fmaxf(s[i][0], s[i][1]), fmaxf(s[i][2], s[i][3]));
            mx = fmaxf(mx, __shfl_xor_sync(0xffffffffu, mx, 8));
            mx = fmaxf(mx, __shfl_xor_sync(0xffffffffu, mx, 4));
            mx = fmaxf(mx, __shfl_xor_sync(0xffffffffu, mx, 2));
            mx = fmaxf(mx, __shfl_xor_sync(0xffffffffu, mx, 1));
            const float mn = fmaxf(m[i], mx);
            float sum = 0.f;
            #pragma unroll
            for (int j = 0; j < 4; j++) {
                const float p = __expf(s[i][j] - mn);
                s[i][j] = p;
                sum += p;
            }
            sum += __shfl_xor_sync(0xffffffffu, sum, 8);
            sum += __shfl_xor_sync(0xffffffffu, sum, 4);
            sum += __shfl_xor_sync(0xffffffffu, sum, 2);
            sum += __shfl_xor_sync(0xffffffffu, sum, 1);
            const float corr = __expf(m[i] - mn);
            l[i] = l[i] * corr + sum;
            m[i] = mn;
            #pragma unroll
            for (int j = 0; j < 4; j++) o[i][j] *= corr;
        }

        // stage P
        #pragma unroll
        for (int i = 0; i < 4; i++)
            #pragma unroll
            for (int j = 0; j < 4; j++)
                Ps[(r0 + i) * 64 + c0 + j] = s[i][j];
        __syncthreads();

        // O += P @ V
        #pragma unroll 4
        for (int kk = 0; kk < 64; kk++) {
            const float a0 = Ps[(r0 + 0) * 64 + kk];
            const float a1 = Ps[(r0 + 1) * 64 + kk];
            const float a2 = Ps[(r0 + 2) * 64 + kk];
            const float a3 = Ps[(r0 + 3) * 64 + kk];
            const float b0 = Vs[kk * 65 + c0 + 0];
            const float b1 = Vs[kk * 65 + c0 + 1];
            const float b2 = Vs[kk * 65 + c0 + 2];
            const float b3 = Vs[kk * 65 + c0 + 3];
            o[0][0] = fmaf(a0, b0, o[0][0]); o[0][1] = fmaf(a0, b1, o[0][1]);
            o[0][2] = fmaf(a0, b2, o[0][2]); o[0][3] = fmaf(a0, b3, o[0][3]);
            o[1][0] = fmaf(a1, b0, o[1][0]); o[1][1] = fmaf(a1, b1, o[1][1]);
            o[1][2] = fmaf(a1, b2, o[1][2]); o[1][3] = fmaf(a1, b3, o[1][3]);
            o[2][0] = fmaf(a2, b0, o[2][0]); o[2][1] = fmaf(a2, b1, o[2][1]);
            o[2][2] = fmaf(a2, b2, o[2][2]); o[2][3] = fmaf(a2, b3, o[2][3]);
            o[3][0] = fmaf(a3, b0, o[3][0]); o[3][1] = fmaf(a3, b1, o[3][1]);
            o[3][2] = fmaf(a3, b2, o[3][2]); o[3][3] = fmaf(a3, b3, o[3][3]);
        }
    }

    float* og = O + base + (size_t)(qt * 64) * DD;
    #pragma unroll
    for (int i = 0; i < 4; i++) {
        const float inv = 1.f / l[i];
        const float4 v = make_float4(o[i][0] * inv, o[i][1] * inv,
                                     o[i][2] * inv, o[i][3] * inv);
        *reinterpret_cast<float4*>(og + (size_t)(r0 + i) * DD + c0) = v;
    }
}

// ---------------- launch ----------------
extern "C" void kernel_launch(void* const* d_in, const int* in_sizes, int n_in,
                              void* d_out, int out_size)
{
    const float* x    = (const float*)d_in[0];
    // d_in[1] = mask (causal, reconstructed analytically — unused)
    const float* wq   = (const float*)d_in[2];
    const float* wk   = (const float*)d_in[3];
    const float* wv   = (const float*)d_in[4];
    const float* wo   = (const float*)d_in[5];
    const float* ln1g = (const float*)d_in[6];
    const float* ln1b = (const float*)d_in[7];
    const float* ln2g = (const float*)d_in[8];
    const float* ln2b = (const float*)d_in[9];
    const float* w1   = (const float*)d_in[10];
    const float* b1   = (const float*)d_in[11];
    const float* wg   = (const float*)d_in[12];
    const float* w2   = (const float*)d_in[13];
    const float* b2   = (const float*)d_in[14];
    float* out = (float*)d_out;

    float *p_ln1, *p_q, *p_k, *p_v, *p_attn, *p_h, *p_ln2, *p_gate, *p_f;
    cudaGetSymbolAddress((void**)&p_ln1,  g_ln1);
    cudaGetSymbolAddress((void**)&p_q,    g_q);
    cudaGetSymbolAddress((void**)&p_k,    g_k);
    cudaGetSymbolAddress((void**)&p_v,    g_v);
    cudaGetSymbolAddress((void**)&p_attn, g_attn);
    cudaGetSymbolAddress((void**)&p_h,    g_h);
    cudaGetSymbolAddress((void**)&p_ln2,  g_ln2);
    cudaGetSymbolAddress((void**)&p_gate, g_gate);
    cudaGetSymbolAddress((void**)&p_f,    g_f);

    const size_t attn_smem = (size_t)ATTN_SMEM_FLOATS * sizeof(float);
    cudaFuncSetAttribute(attn_kernel, cudaFuncAttributeMaxDynamicSharedMemorySize,
                         (int)attn_smem);

    // 1) ln1
    ln_kernel<<<NROWS, 256>>>(x, ln1g, ln1b, p_ln1);

    // 2) Q, K, V projections
    dim3 gQKV(DD / 128, NROWS / 128);
    sgemm_nt<<<gQKV, 256>>>(p_ln1, wq, p_q, NROWS, DD, DD, nullptr, nullptr, nullptr, EP_NONE);
    sgemm_nt<<<gQKV, 256>>>(p_ln1, wk, p_k, NROWS, DD, DD, nullptr, nullptr, nullptr, EP_NONE);
    sgemm_nt<<<gQKV, 256>>>(p_ln1, wv, p_v, NROWS, DD, DD, nullptr, nullptr, nullptr, EP_NONE);

    // 3) causal flash attention
    dim3 gAttn(LL / 64, BB * HH);
    attn_kernel<<<gAttn, 256, attn_smem>>>(p_q, p_k, p_v, p_attn);

    // 4) output projection + residual -> h
    sgemm_nt<<<gQKV, 256>>>(p_attn, wo, p_h, NROWS, DD, DD, nullptr, x, nullptr, EP_RES);

    // 5) ln2
    ln_kernel<<<NROWS, 256>>>(p_h, ln2g, ln2b, p_ln2);

    // 6) gate = ln2 @ wg^T
    dim3 gFFN(HIDD / 128, NROWS / 128);
    sgemm_nt<<<gFFN, 256>>>(p_ln2, wg, p_gate, NROWS, HIDD, DD, nullptr, nullptr, nullptr, EP_NONE);

    // 7) f = silu(ln2 @ w1^T + b1) * gate
    sgemm_nt<<<gFFN, 256>>>(p_ln2, w1, p_f, NROWS, HIDD, DD, b1, nullptr, p_gate, EP_SILU_MUL);

    // 8) out = f @ w2^T + b2 + h
    dim3 gOut(DD / 128, NROWS / 128);
    sgemm_nt<<<gOut, 256>>>(p_f, w2, out, NROWS, DD, HIDD, b2, p_h, nullptr, EP_BIAS_RES);
}

// round 2
// speedup vs baseline: 2.5098x; 2.5098x over previous
#include <cuda_runtime.h>
#include <math.h>
#include <stdint.h>

#define BB 2
#define LL 2048
#define DD 1024
#define HH 16
#define HDIM 64
#define HIDD 4096
#define NROWS (BB*LL)   // 4096

// ---------------- scratch (static device globals; no allocation) ----------------
__device__ float g_ln1 [NROWS*DD];
__device__ float g_q   [NROWS*DD];
__device__ float g_k   [NROWS*DD];
__device__ float g_v   [NROWS*DD];
__device__ float g_attn[NROWS*DD];
__device__ float g_h   [NROWS*DD];
__device__ float g_ln2 [NROWS*DD];
__device__ float g_gate[(size_t)NROWS*HIDD];
__device__ float g_f   [(size_t)NROWS*HIDD];

// ---------------- LayerNorm: one block per row of 1024 ----------------
__global__ __launch_bounds__(256) void ln_kernel(const float* __restrict__ x,
                                                 const float* __restrict__ gamma,
                                                 const float* __restrict__ beta,
                                                 float* __restrict__ y)
{
    const int row = blockIdx.x;
    const int tid = threadIdx.x;
    const float4 v = reinterpret_cast<const float4*>(x + (size_t)row * DD)[tid];
    float s = v.x + v.y + v.z + v.w;
    float q = v.x*v.x + v.y*v.y + v.z*v.z + v.w*v.w;
    #pragma unroll
    for (int o = 16; o >= 1; o >>= 1) {
        s += __shfl_xor_sync(0xffffffffu, s, o);
        q += __shfl_xor_sync(0xffffffffu, q, o);
    }
    __shared__ float ss[8], sq[8];
    __shared__ float stats[2];
    const int wid = tid >> 5;
    if ((tid & 31) == 0) { ss[wid] = s; sq[wid] = q; }
    __syncthreads();
    if (tid == 0) {
        float ts = 0.f, tq = 0.f;
        #pragma unroll
        for (int i = 0; i < 8; i++) { ts += ss[i]; tq += sq[i]; }
        float mu  = ts * (1.0f / DD);
        float var = tq * (1.0f / DD) - mu * mu;
        stats[0] = mu;
        stats[1] = rsqrtf(var + 1e-5f);
    }
    __syncthreads();
    const float mu = stats[0], rs = stats[1];
    const float4 g4 = reinterpret_cast<const float4*>(gamma)[tid];
    const float4 b4 = reinterpret_cast<const float4*>(beta)[tid];
    float4 o;
    o.x = (v.x - mu) * rs * g4.x + b4.x;
    o.y = (v.y - mu) * rs * g4.y + b4.y;
    o.z = (v.z - mu) * rs * g4.z + b4.z;
    o.w = (v.w - mu) * rs * g4.w + b4.w;
    reinterpret_cast<float4*>(y + (size_t)row * DD)[tid] = o;
}

// ---------------- TF32 tensor-core GEMM (NT): C[M,N] = A[M,K] @ W[N,K]^T ----------------
#define EP_NONE     0
#define EP_RES      1   // C = acc + res
#define EP_SILU_MUL 2   // C = silu(acc + bias[col]) * mul
#define EP_BIAS_RES 3   // C = acc + bias[col] + res

#define SSTR 20   // smem row stride (floats): 16 + 4 pad -> conflict-free frag gather, 16B-aligned rows

__device__ __forceinline__ uint32_t f2tf32(float f) {
    uint32_t u;
    asm("cvt.rna.tf32.f32 %0, %1;" : "=r"(u) : "f"(f));
    return u;
}

__device__ __forceinline__ void cp16(uint32_t saddr, const float* gaddr) {
    asm volatile("cp.async.cg.shared.global [%0], [%1], 16;" :: "r"(saddr), "l"(gaddr));
}

__device__ __forceinline__ void mma_tf32(float c[4],
                                         const uint32_t a[4], const uint32_t b[2]) {
    asm volatile(
        "mma.sync.aligned.m16n8k8.row.col.f32.tf32.tf32.f32 "
        "{%0,%1,%2,%3}, {%4,%5,%6,%7}, {%8,%9}, {%0,%1,%2,%3};"
        : "+f"(c[0]), "+f"(c[1]), "+f"(c[2]), "+f"(c[3])
        : "r"(a[0]), "r"(a[1]), "r"(a[2]), "r"(a[3]), "r"(b[0]), "r"(b[1]));
}

__global__ __launch_bounds__(256, 2) void mma_gemm_nt(
    const float* __restrict__ A, const float* __restrict__ W,
    float* __restrict__ C, int M, int N, int K,
    const float* __restrict__ bias, const float* __restrict__ res,
    const float* __restrict__ mul, int mode)
{
    __shared__ float As[2][128 * SSTR];
    __shared__ float Bs[2][128 * SSTR];

    const int tid  = threadIdx.x;
    const int lane = tid & 31;
    const int warp = tid >> 5;
    const int g    = lane >> 2;      // group 0..7
    const int t4   = lane & 3;       // thread-in-group
    const int wm   = (warp >> 2) * 64;   // warp row origin in tile
    const int wn   = (warp & 3)  * 32;   // warp col origin in tile
    const int row0 = blockIdx.y * 128;
    const int col0 = blockIdx.x * 128;

    // loader mapping: 512 float4 per operand per stage; thread does 2 each
    const int lrow = tid >> 2;           // 0..63
    const int lc   = (tid & 3) * 4;      // 0,4,8,12

    const float* gA0 = A + (size_t)(row0 + lrow) * K + lc;
    const float* gA1 = gA0 + (size_t)64 * K;
    const float* gW0 = W + (size_t)(col0 + lrow) * K + lc;
    const float* gW1 = gW0 + (size_t)64 * K;

    const uint32_t sA0 = (uint32_t)__cvta_generic_to_shared(&As[0][lrow * SSTR + lc]);
    const uint32_t sA1 = (uint32_t)__cvta_generic_to_shared(&As[0][(lrow + 64) * SSTR + lc]);
    const uint32_t sB0 = (uint32_t)__cvta_generic_to_shared(&Bs[0][lrow * SSTR + lc]);
    const uint32_t sB1 = (uint32_t)__cvta_generic_to_shared(&Bs[0][(lrow + 64) * SSTR + lc]);
    const uint32_t stageA = (uint32_t)(128 * SSTR * sizeof(float));
    const uint32_t stageB = stageA;

    float acc[4][4][4];
    #pragma unroll
    for (int mt = 0; mt < 4; mt++)
        #pragma unroll
        for (int nt = 0; nt < 4; nt++)
            #pragma unroll
            for (int i = 0; i < 4; i++) acc[mt][nt][i] = 0.f;

    const int nk = K >> 4;   // BK = 16

    // prologue: stage 0
    cp16(sA0, gA0); cp16(sA1, gA1); cp16(sB0, gW0); cp16(sB1, gW1);
    asm volatile("cp.async.commit_group;");

    for (int kt = 0; kt < nk; kt++) {
        const int s = kt & 1;
        if (kt + 1 < nk) {
            const int ko = (kt + 1) << 4;
            const uint32_t so = (uint32_t)((kt + 1) & 1) * stageA;
            cp16(sA0 + so, gA0 + ko); cp16(sA1 + so, gA1 + ko);
            cp16(sB0 + so, gW0 + ko); cp16(sB1 + so, gW1 + ko);
        }
        asm volatile("cp.async.commit_group;");
        asm volatile("cp.async.wait_group 1;");
        __syncthreads();

        const float* as = As[s];
        const float* bs = Bs[s];
        #pragma unroll
        for (int ks = 0; ks < 2; ks++) {
            const int kb = ks * 8;
            uint32_t af[4][4];
            uint32_t bf[4][2];
            #pragma unroll
            for (int mt = 0; mt < 4; mt++) {
                const float* p = &as[(wm + mt * 16 + g) * SSTR + kb + t4];
                af[mt][0] = f2tf32(p[0]);
                af[mt][1] = f2tf32(p[8 * SSTR]);
                af[mt][2] = f2tf32(p[4]);
                af[mt][3] = f2tf32(p[8 * SSTR + 4]);
            }
            #pragma unroll
            for (int nt = 0; nt < 4; nt++) {
                const float* p = &bs[(wn + nt * 8 + g) * SSTR + kb + t4];
                bf[nt][0] = f2tf32(p[0]);
                bf[nt][1] = f2tf32(p[4]);
            }
            #pragma unroll
            for (int mt = 0; mt < 4; mt++)
                #pragma unroll
                for (int nt = 0; nt < 4; nt++)
                    mma_tf32(acc[mt][nt], af[mt], bf[nt]);
        }
        __syncthreads();
    }

    // ---------------- epilogue ----------------
    #pragma unroll
    for (int mt = 0; mt < 4; mt++) {
        #pragma unroll
        for (int nt = 0; nt < 4; nt++) {
            const int r = row0 + wm + mt * 16 + g;
            const int c = col0 + wn + nt * 8 + 2 * t4;
            const size_t i0 = (size_t)r * N + c;
            const size_t i1 = i0 + (size_t)8 * N;
            float v00 = acc[mt][nt][0], v01 = acc[mt][nt][1];
            float v10 = acc[mt][nt][2], v11 = acc[mt][nt][3];

            if (mode == EP_RES) {
                const float2 r0v = *reinterpret_cast<const float2*>(&res[i0]);
                const float2 r1v = *reinterpret_cast<const float2*>(&res[i1]);
                v00 += r0v.x; v01 += r0v.y; v10 += r1v.x; v11 += r1v.y;
            } else if (mode == EP_SILU_MUL) {
                const float2 bb  = *reinterpret_cast<const float2*>(&bias[c]);
                const float2 m0v = *reinterpret_cast<const float2*>(&mul[i0]);
                const float2 m1v = *reinterpret_cast<const float2*>(&mul[i1]);
                float x;
                x = v00 + bb.x; v00 = x / (1.f + __expf(-x)) * m0v.x;
                x = v01 + bb.y; v01 = x / (1.f + __expf(-x)) * m0v.y;
                x = v10 + bb.x; v10 = x / (1.f + __expf(-x)) * m1v.x;
                x = v11 + bb.y; v11 = x / (1.f + __expf(-x)) * m1v.y;
            } else if (mode == EP_BIAS_RES) {
                const float2 bb  = *reinterpret_cast<const float2*>(&bias[c]);
                const float2 r0v = *reinterpret_cast<const float2*>(&res[i0]);
                const float2 r1v = *reinterpret_cast<const float2*>(&res[i1]);
                v00 += bb.x + r0v.x; v01 += bb.y + r0v.y;
                v10 += bb.x + r1v.x; v11 += bb.y + r1v.y;
            }
            *reinterpret_cast<float2*>(&C[i0]) = make_float2(v00, v01);
            *reinterpret_cast<float2*>(&C[i1]) = make_float2(v10, v11);
        }
    }
}

// ---------------- Causal flash attention, BQ=BK=64, HD=64 ----------------
#define ATTN_SMEM_FLOATS (64*64 + 64*64 + 64*65 + 64*65)

__global__ __launch_bounds__(256) void attn_kernel(
    const float* __restrict__ Q, const float* __restrict__ Kx,
    const float* __restrict__ V, float* __restrict__ O)
{
    extern __shared__ float sm[];
    float* Qs = sm;               // [64][64]
    float* Ps = Qs + 64 * 64;     // [64][64]
    float* Ks = Ps + 64 * 64;     // [64][65]
    float* Vs = Ks + 64 * 65;     // [64][65]

    const int tid = threadIdx.x;
    const int qt  = blockIdx.x;
    const int bh  = blockIdx.y;
    const int b   = bh >> 4, h = bh & 15;
    const int ty  = tid >> 4, tx = tid & 15;
    const int r0  = ty * 4, c0 = tx * 4;

    const size_t base = ((size_t)b * LL) * DD + (size_t)h * HDIM;
    const float* qg = Q + base + (size_t)(qt * 64) * DD;

    for (int e = tid; e < 64 * 16; e += 256) {
        const int r = e >> 4, c4 = (e & 15) << 2;
        const float4 v = *reinterpret_cast<const float4*>(qg + (size_t)r * DD + c4);
        *reinterpret_cast<float4*>(&Qs[r * 64 + c4]) = v;
    }

    float o[4][4];
    float m[4], l[4];
    #pragma unroll
    for (int i = 0; i < 4; i++) {
        m[i] = -1e30f; l[i] = 0.f;
        #pragma unroll
        for (int j = 0; j < 4; j++) o[i][j] = 0.f;
    }

    for (int kt = 0; kt <= qt; kt++) {
        const float* kg = Kx + base + (size_t)(kt * 64) * DD;
        const float* vg = V  + base + (size_t)(kt * 64) * DD;
        __syncthreads();
        for (int e = tid; e < 64 * 16; e += 256) {
            const int r = e >> 4, c4 = (e & 15) << 2;
            const float4 kv = *reinterpret_cast<const float4*>(kg + (size_t)r * DD + c4);
            const float4 vv = *reinterpret_cast<const float4*>(vg + (size_t)r * DD + c4);
            Ks[r * 65 + c4 + 0] = kv.x; Ks[r * 65 + c4 + 1] = kv.y;
            Ks[r * 65 + c4 + 2] = kv.z; Ks[r * 65 + c4 + 3] = kv.w;
            Vs[r * 65 + c4 + 0] = vv.x; Vs[r * 65 + c4 + 1] = vv.y;
            Vs[r * 65 + c4 + 2] = vv.z; Vs[r * 65 + c4 + 3] = vv.w;
        }
        __syncthreads();

        float s[4][4];
        #pragma unroll
        for (int i = 0; i < 4; i++)
            #pragma unroll
            for (int j = 0; j < 4; j++) s[i][j] = 0.f;

        #pragma unroll 4
        for (int d = 0; d < 64; d++) {
            const float a0 = Qs[(r0 + 0) * 64 + d];
            const float a1 = Qs[(r0 + 1) * 64 + d];
            const float a2 = Qs[(r0 + 2) * 64 + d];
            const float a3 = Qs[(r0 + 3) * 64 + d];
            const float b0 = Ks[(c0 + 0) * 65 + d];
            const float b1 = Ks[(c0 + 1) * 65 + d];
            const float b2 = Ks[(c0 + 2) * 65 + d];
            const float b3 = Ks[(c0 + 3) * 65 + d];
            s[0][0] = fmaf(a0, b0, s[0][0]); s[0][1] = fmaf(a0, b1, s[0][1]);
            s[0][2] = fmaf(a0, b2, s[0][2]); s[0][3] = fmaf(a0, b3, s[0][3]);
            s[1][0] = fmaf(a1, b0, s[1][0]); s[1][1] = fmaf(a1, b1, s[1][1]);
            s[1][2] = fmaf(a1, b2, s[1][2]); s[1][3] = fmaf(a1, b3, s[1][3]);
            s[2][0] = fmaf(a2, b0, s[2][0]); s[2][1] = fmaf(a2, b1, s[2][1]);
            s[2][2] = fmaf(a2, b2, s[2][2]); s[2][3] = fmaf(a2, b3, s[2][3]);
            s[3][0] = fmaf(a3, b0, s[3][0]); s[3][1] = fmaf(a3, b1, s[3][1]);
            s[3][2] = fmaf(a3, b2, s[3][2]); s[3][3] = fmaf(a3, b3, s[3][3]);
        }

        #pragma unroll
        for (int i = 0; i < 4; i++)
            #pragma unroll
            for (int j = 0; j < 4; j++) {
                float val = s[i][j] * 0.125f + 0.01f * (float)(kt * 64 + c0 + j);
                if (kt == qt && (c0 + j) > (r0 + i)) val = -1e30f;
                s[i][j] = val;
            }

        #pragma unroll
        for (int i = 0; i < 4; i++) {
            float mx = fmaxf(fmaxf(s[i][0], s[i][1]), fmaxf(s[i][2], s[i][3]));
            mx = fmaxf(mx, __shfl_xor_sync(0xffffffffu, mx, 8));
            mx = fmaxf(mx, __shfl_xor_sync(0xffffffffu, mx, 4));
            mx = fmaxf(mx, __shfl_xor_sync(0xffffffffu, mx, 2));
            mx = fmaxf(mx, __shfl_xor_sync(0xffffffffu, mx, 1));
            const float mn = fmaxf(m[i], mx);
            float sum = 0.f;
            #pragma unroll
            for (int j = 0; j < 4; j++) {
                const float p = __expf(s[i][j] - mn);
                s[i][j] = p;
                sum += p;
            }
            sum += __shfl_xor_sync(0xffffffffu, sum, 8);
            sum += __shfl_xor_sync(0xffffffffu, sum, 4);
            sum += __shfl_xor_sync(0xffffffffu, sum, 2);
            sum += __shfl_xor_sync(0xffffffffu, sum, 1);
            const float corr = __expf(m[i] - mn);
            l[i] = l[i] * corr + sum;
            m[i] = mn;
            #pragma unroll
            for (int j = 0; j < 4; j++) o[i][j] *= corr;
        }

        #pragma unroll
        for (int i = 0; i < 4; i++)
            #pragma unroll
            for (int j = 0; j < 4; j++)
                Ps[(r0 + i) * 64 + c0 + j] = s[i][j];
        __syncthreads();

        #pragma unroll 4
        for (int kk = 0; kk < 64; kk++) {
            const float a0 = Ps[(r0 + 0) * 64 + kk];
            const float a1 = Ps[(r0 + 1) * 64 + kk];
            const float a2 = Ps[(r0 + 2) * 64 + kk];
            const float a3 = Ps[(r0 + 3) * 64 + kk];
            const float b0 = Vs[kk * 65 + c0 + 0];
            const float b1 = Vs[kk * 65 + c0 + 1];
            const float b2 = Vs[kk * 65 + c0 + 2];
            const float b3 = Vs[kk * 65 + c0 + 3];
            o[0][0] = fmaf(a0, b0, o[0][0]); o[0][1] = fmaf(a0, b1, o[0][1]);
            o[0][2] = fmaf(a0, b2, o[0][2]); o[0][3] = fmaf(a0, b3, o[0][3]);
            o[1][0] = fmaf(a1, b0, o[1][0]); o[1][1] = fmaf(a1, b1, o[1][1]);
            o[1][2] = fmaf(a1, b2, o[1][2]); o[1][3] = fmaf(a1, b3, o[1][3]);
            o[2][0] = fmaf(a2, b0, o[2][0]); o[2][1] = fmaf(a2, b1, o[2][1]);
            o[2][2] = fmaf(a2, b2, o[2][2]); o[2][3] = fmaf(a2, b3, o[2][3]);
            o[3][0] = fmaf(a3, b0, o[3][0]); o[3][1] = fmaf(a3, b1, o[3][1]);
            o[3][2] = fmaf(a3, b2, o[3][2]); o[3][3] = fmaf(a3, b3, o[3][3]);
        }
    }

    float* og = O + base + (size_t)(qt * 64) * DD;
    #pragma unroll
    for (int i = 0; i < 4; i++) {
        const float inv = 1.f / l[i];
        const float4 v = make_float4(o[i][0] * inv, o[i][1] * inv,
                                     o[i][2] * inv, o[i][3] * inv);
        *reinterpret_cast<float4*>(og + (size_t)(r0 + i) * DD + c0) = v;
    }
}

// ---------------- launch ----------------
extern "C" void kernel_launch(void* const* d_in, const int* in_sizes, int n_in,
                              void* d_out, int out_size)
{
    const float* x    = (const float*)d_in[0];
    const float* wq   = (const float*)d_in[2];
    const float* wk   = (const float*)d_in[3];
    const float* wv   = (const float*)d_in[4];
    const float* wo   = (const float*)d_in[5];
    const float* ln1g = (const float*)d_in[6];
    const float* ln1b = (const float*)d_in[7];
    const float* ln2g = (const float*)d_in[8];
    const float* ln2b = (const float*)d_in[9];
    const float* w1   = (const float*)d_in[10];
    const float* b1   = (const float*)d_in[11];
    const float* wg   = (const float*)d_in[12];
    const float* w2   = (const float*)d_in[13];
    const float* b2   = (const float*)d_in[14];
    float* out = (float*)d_out;

    float *p_ln1, *p_q, *p_k, *p_v, *p_attn, *p_h, *p_ln2, *p_gate, *p_f;
    cudaGetSymbolAddress((void**)&p_ln1,  g_ln1);
    cudaGetSymbolAddress((void**)&p_q,    g_q);
    cudaGetSymbolAddress((void**)&p_k,    g_k);
    cudaGetSymbolAddress((void**)&p_v,    g_v);
    cudaGetSymbolAddress((void**)&p_attn, g_attn);
    cudaGetSymbolAddress((void**)&p_h,    g_h);
    cudaGetSymbolAddress((void**)&p_ln2,  g_ln2);
    cudaGetSymbolAddress((void**)&p_gate, g_gate);
    cudaGetSymbolAddress((void**)&p_f,    g_f);

    const size_t attn_smem = (size_t)ATTN_SMEM_FLOATS * sizeof(float);
    cudaFuncSetAttribute(attn_kernel, cudaFuncAttributeMaxDynamicSharedMemorySize,
                         (int)attn_smem);

    // 1) ln1
    ln_kernel<<<NROWS, 256>>>(x, ln1g, ln1b, p_ln1);

    // 2) Q, K, V projections (tensor cores, tf32)
    dim3 gQKV(DD / 128, NROWS / 128);
    mma_gemm_nt<<<gQKV, 256>>>(p_ln1, wq, p_q, NROWS, DD, DD, nullptr, nullptr, nullptr, EP_NONE);
    mma_gemm_nt<<<gQKV, 256>>>(p_ln1, wk, p_k, NROWS, DD, DD, nullptr, nullptr, nullptr, EP_NONE);
    mma_gemm_nt<<<gQKV, 256>>>(p_ln1, wv, p_v, NROWS, DD, DD, nullptr, nullptr, nullptr, EP_NONE);

    // 3) causal flash attention
    dim3 gAttn(LL / 64, BB * HH);
    attn_kernel<<<gAttn, 256, attn_smem>>>(p_q, p_k, p_v, p_attn);

    // 4) output projection + residual -> h
    mma_gemm_nt<<<gQKV, 256>>>(p_attn, wo, p_h, NROWS, DD, DD, nullptr, x, nullptr, EP_RES);

    // 5) ln2
    ln_kernel<<<NROWS, 256>>>(p_h, ln2g, ln2b, p_ln2);

    // 6) gate = ln2 @ wg^T
    dim3 gFFN(HIDD / 128, NROWS / 128);
    mma_gemm_nt<<<gFFN, 256>>>(p_ln2, wg, p_gate, NROWS, HIDD, DD, nullptr, nullptr, nullptr, EP_NONE);

    // 7) f = silu(ln2 @ w1^T + b1) * gate
    mma_gemm_nt<<<gFFN, 256>>>(p_ln2, w1, p_f, NROWS, HIDD, DD, b1, nullptr, p_gate, EP_SILU_MUL);

    // 8) out = f @ w2^T + b2 + h
    dim3 gOut(DD / 128, NROWS / 128);
    mma_gemm_nt<<<gOut, 256>>>(p_f, w2, out, NROWS, DD, HIDD, b2, p_h, nullptr, EP_BIAS_RES);
}

// round 3
// speedup vs baseline: 3.4731x; 1.3838x over previous
#include <cuda_runtime.h>
#include <math.h>
#include <stdint.h>

#define BB 2
#define LL 2048
#define DD 1024
#define HH 16
#define HDIM 64
#define HIDD 4096
#define NROWS (BB*LL)   // 4096

// ---------------- scratch (static device globals; no allocation) ----------------
__device__ float g_ln1 [NROWS*DD];
__device__ float g_q   [NROWS*DD];
__device__ float g_k   [NROWS*DD];
__device__ float g_v   [NROWS*DD];
__device__ float g_attn[NROWS*DD];
__device__ float g_h   [NROWS*DD];
__device__ float g_ln2 [NROWS*DD];
__device__ float g_gate[(size_t)NROWS*HIDD];
__device__ float g_f   [(size_t)NROWS*HIDD];

// ---------------- common PTX helpers ----------------
__device__ __forceinline__ void cp16(uint32_t saddr, const float* gaddr) {
    asm volatile("cp.async.cg.shared.global [%0], [%1], 16;" :: "r"(saddr), "l"(gaddr));
}
__device__ __forceinline__ void mma_tf32(float c[4],
                                         const uint32_t a[4], const uint32_t b[2]) {
    asm volatile(
        "mma.sync.aligned.m16n8k8.row.col.f32.tf32.tf32.f32 "
        "{%0,%1,%2,%3}, {%4,%5,%6,%7}, {%8,%9}, {%0,%1,%2,%3};"
        : "+f"(c[0]), "+f"(c[1]), "+f"(c[2]), "+f"(c[3])
        : "r"(a[0]), "r"(a[1]), "r"(a[2]), "r"(a[3]), "r"(b[0]), "r"(b[1]));
}

// ---------------- LayerNorm ----------------
__global__ __launch_bounds__(256) void ln_kernel(const float* __restrict__ x,
                                                 const float* __restrict__ gamma,
                                                 const float* __restrict__ beta,
                                                 float* __restrict__ y)
{
    const int row = blockIdx.x;
    const int tid = threadIdx.x;
    const float4 v = reinterpret_cast<const float4*>(x + (size_t)row * DD)[tid];
    float s = v.x + v.y + v.z + v.w;
    float q = v.x*v.x + v.y*v.y + v.z*v.z + v.w*v.w;
    #pragma unroll
    for (int o = 16; o >= 1; o >>= 1) {
        s += __shfl_xor_sync(0xffffffffu, s, o);
        q += __shfl_xor_sync(0xffffffffu, q, o);
    }
    __shared__ float ss[8], sq[8];
    __shared__ float stats[2];
    const int wid = tid >> 5;
    if ((tid & 31) == 0) { ss[wid] = s; sq[wid] = q; }
    __syncthreads();
    if (tid == 0) {
        float ts = 0.f, tq = 0.f;
        #pragma unroll
        for (int i = 0; i < 8; i++) { ts += ss[i]; tq += sq[i]; }
        float mu  = ts * (1.0f / DD);
        float var = tq * (1.0f / DD) - mu * mu;
        stats[0] = mu;
        stats[1] = rsqrtf(var + 1e-5f);
    }
    __syncthreads();
    const float mu = stats[0], rs = stats[1];
    const float4 g4 = reinterpret_cast<const float4*>(gamma)[tid];
    const float4 b4 = reinterpret_cast<const float4*>(beta)[tid];
    float4 o;
    o.x = (v.x - mu) * rs * g4.x + b4.x;
    o.y = (v.y - mu) * rs * g4.y + b4.y;
    o.z = (v.z - mu) * rs * g4.z + b4.z;
    o.w = (v.w - mu) * rs * g4.w + b4.w;
    reinterpret_cast<float4*>(y + (size_t)row * DD)[tid] = o;
}

// ---------------- TF32 tensor-core GEMM (NT) ----------------
#define EP_NONE     0
#define EP_RES      1
#define EP_SILU_MUL 2
#define EP_BIAS_RES 3
#define SSTR 20

__global__ __launch_bounds__(256, 2) void mma_gemm_nt(
    const float* __restrict__ A, const float* __restrict__ W,
    float* __restrict__ C, int M, int N, int K,
    const float* __restrict__ bias, const float* __restrict__ res,
    const float* __restrict__ mul, int mode)
{
    __shared__ float As[2][128 * SSTR];
    __shared__ float Bs[2][128 * SSTR];

    const int tid  = threadIdx.x;
    const int lane = tid & 31;
    const int warp = tid >> 5;
    const int g    = lane >> 2;
    const int t4   = lane & 3;
    const int wm   = (warp >> 2) * 64;
    const int wn   = (warp & 3)  * 32;
    const int row0 = blockIdx.y * 128;
    const int col0 = blockIdx.x * 128;

    const int lrow = tid >> 2;
    const int lc   = (tid & 3) * 4;

    const float* gA0 = A + (size_t)(row0 + lrow) * K + lc;
    const float* gA1 = gA0 + (size_t)64 * K;
    const float* gW0 = W + (size_t)(col0 + lrow) * K + lc;
    const float* gW1 = gW0 + (size_t)64 * K;

    const uint32_t sA0 = (uint32_t)__cvta_generic_to_shared(&As[0][lrow * SSTR + lc]);
    const uint32_t sA1 = (uint32_t)__cvta_generic_to_shared(&As[0][(lrow + 64) * SSTR + lc]);
    const uint32_t sB0 = (uint32_t)__cvta_generic_to_shared(&Bs[0][lrow * SSTR + lc]);
    const uint32_t sB1 = (uint32_t)__cvta_generic_to_shared(&Bs[0][(lrow + 64) * SSTR + lc]);
    const uint32_t stageA = (uint32_t)(128 * SSTR * sizeof(float));

    float acc[4][4][4];
    #pragma unroll
    for (int mt = 0; mt < 4; mt++)
        #pragma unroll
        for (int nt = 0; nt < 4; nt++)
            #pragma unroll
            for (int i = 0; i < 4; i++) acc[mt][nt][i] = 0.f;

    const int nk = K >> 4;

    cp16(sA0, gA0); cp16(sA1, gA1); cp16(sB0, gW0); cp16(sB1, gW1);
    asm volatile("cp.async.commit_group;");

    for (int kt = 0; kt < nk; kt++) {
        const int s = kt & 1;
        if (kt + 1 < nk) {
            const int ko = (kt + 1) << 4;
            const uint32_t so = (uint32_t)((kt + 1) & 1) * stageA;
            cp16(sA0 + so, gA0 + ko); cp16(sA1 + so, gA1 + ko);
            cp16(sB0 + so, gW0 + ko); cp16(sB1 + so, gW1 + ko);
        }
        asm volatile("cp.async.commit_group;");
        asm volatile("cp.async.wait_group 1;");
        __syncthreads();

        const float* as = As[s];
        const float* bs = Bs[s];
        #pragma unroll
        for (int ks = 0; ks < 2; ks++) {
            const int kb = ks * 8;
            uint32_t af[4][4];
            uint32_t bf[4][2];
            #pragma unroll
            for (int mt = 0; mt < 4; mt++) {
                const float* p = &as[(wm + mt * 16 + g) * SSTR + kb + t4];
                af[mt][0] = __float_as_uint(p[0]);
                af[mt][1] = __float_as_uint(p[8 * SSTR]);
                af[mt][2] = __float_as_uint(p[4]);
                af[mt][3] = __float_as_uint(p[8 * SSTR + 4]);
            }
            #pragma unroll
            for (int nt = 0; nt < 4; nt++) {
                const float* p = &bs[(wn + nt * 8 + g) * SSTR + kb + t4];
                bf[nt][0] = __float_as_uint(p[0]);
                bf[nt][1] = __float_as_uint(p[4]);
            }
            #pragma unroll
            for (int mt = 0; mt < 4; mt++)
                #pragma unroll
                for (int nt = 0; nt < 4; nt++)
                    mma_tf32(acc[mt][nt], af[mt], bf[nt]);
        }
        __syncthreads();
    }

    #pragma unroll
    for (int mt = 0; mt < 4; mt++) {
        #pragma unroll
        for (int nt = 0; nt < 4; nt++) {
            const int r = row0 + wm + mt * 16 + g;
            const int c = col0 + wn + nt * 8 + 2 * t4;
            const size_t i0 = (size_t)r * N + c;
            const size_t i1 = i0 + (size_t)8 * N;
            float v00 = acc[mt][nt][0], v01 = acc[mt][nt][1];
            float v10 = acc[mt][nt][2], v11 = acc[mt][nt][3];

            if (mode == EP_RES) {
                const float2 r0v = *reinterpret_cast<const float2*>(&res[i0]);
                const float2 r1v = *reinterpret_cast<const float2*>(&res[i1]);
                v00 += r0v.x; v01 += r0v.y; v10 += r1v.x; v11 += r1v.y;
            } else if (mode == EP_SILU_MUL) {
                const float2 bb  = *reinterpret_cast<const float2*>(&bias[c]);
                const float2 m0v = *reinterpret_cast<const float2*>(&mul[i0]);
                const float2 m1v = *reinterpret_cast<const float2*>(&mul[i1]);
                float x;
                x = v00 + bb.x; v00 = x / (1.f + __expf(-x)) * m0v.x;
                x = v01 + bb.y; v01 = x / (1.f + __expf(-x)) * m0v.y;
                x = v10 + bb.x; v10 = x / (1.f + __expf(-x)) * m1v.x;
                x = v11 + bb.y; v11 = x / (1.f + __expf(-x)) * m1v.y;
            } else if (mode == EP_BIAS_RES) {
                const float2 bb  = *reinterpret_cast<const float2*>(&bias[c]);
                const float2 r0v = *reinterpret_cast<const float2*>(&res[i0]);
                const float2 r1v = *reinterpret_cast<const float2*>(&res[i1]);
                v00 += bb.x + r0v.x; v01 += bb.y + r0v.y;
                v10 += bb.x + r1v.x; v11 += bb.y + r1v.y;
            }
            *reinterpret_cast<float2*>(&C[i0]) = make_float2(v00, v01);
            *reinterpret_cast<float2*>(&C[i1]) = make_float2(v10, v11);
        }
    }
}

// ---------------- Tensor-core causal flash attention ----------------
// BQ=128 (8 warps x 16 rows), BK=64, HD=64. tf32 mma for S=QK^T and O+=PV.
#define AT_KS 68
#define AT_VS 72
#define AT_PS 68
#define ATTN_SMEM_BYTES ((64*AT_KS + 64*AT_VS + 128*AT_PS) * 4)

__global__ __launch_bounds__(256) void attn_mma(
    const float* __restrict__ Q, const float* __restrict__ Kx,
    const float* __restrict__ V, float* __restrict__ O)
{
    extern __shared__ float sm[];
    float* Ks = sm;                    // [64][AT_KS]
    float* Vs = Ks + 64 * AT_KS;       // [64][AT_VS]
    float* Ps = Vs + 64 * AT_VS;       // [128][AT_PS]

    const int tid  = threadIdx.x;
    const int lane = tid & 31;
    const int warp = tid >> 5;         // 0..7
    const int g    = lane >> 2;        // 0..7
    const int t4   = lane & 3;         // 0..3

    const int qt = blockIdx.x;         // 128-row query tile
    const int bh = blockIdx.y;
    const int b  = bh >> 4, h = bh & 15;
    const size_t base = ((size_t)b * LL) * DD + (size_t)h * HDIM;

    const int qrow0 = qt * 128 + warp * 16;   // warp's first global q row
    const int grow0 = qrow0 + g;              // thread row A
    const int grow1 = grow0 + 8;              // thread row B

    // Q fragments in registers for the whole block: 8 k-tiles x 4 regs
    uint32_t qf[8][4];
    {
        const float* qg = Q + base;
        #pragma unroll
        for (int kd = 0; kd < 8; kd++) {
            const int c = kd * 8 + t4;
            qf[kd][0] = __float_as_uint(qg[(size_t)grow0 * DD + c]);
            qf[kd][1] = __float_as_uint(qg[(size_t)grow1 * DD + c]);
            qf[kd][2] = __float_as_uint(qg[(size_t)grow0 * DD + c + 4]);
            qf[kd][3] = __float_as_uint(qg[(size_t)grow1 * DD + c + 4]);
        }
    }

    float oa[8][4];
    #pragma unroll
    for (int nt = 0; nt < 8; nt++)
        #pragma unroll
        for (int i = 0; i < 4; i++) oa[nt][i] = 0.f;
    float m0 = -1e30f, m1 = -1e30f, l0 = 0.f, l1 = 0.f;

    const uint32_t sKs = (uint32_t)__cvta_generic_to_shared(Ks);
    const uint32_t sVs = (uint32_t)__cvta_generic_to_shared(Vs);

    const int ktmax = 2 * qt + 1;
    for (int kt = 0; kt <= ktmax; kt++) {
        __syncthreads();   // previous iter's consumers done before overwrite
        // load K,V tiles (64x64) via cp.async
        {
            const float* kg = Kx + base + (size_t)(kt * 64) * DD;
            const float* vg = V  + base + (size_t)(kt * 64) * DD;
            #pragma unroll
            for (int i = 0; i < 4; i++) {
                const int idx = tid + i * 256;       // 0..1023
                const int r = idx >> 4;
                const int c = (idx & 15) << 2;
                cp16(sKs + (uint32_t)(r * AT_KS + c) * 4, kg + (size_t)r * DD + c);
                cp16(sVs + (uint32_t)(r * AT_VS + c) * 4, vg + (size_t)r * DD + c);
            }
            asm volatile("cp.async.commit_group;");
            asm volatile("cp.async.wait_group 0;");
            __syncthreads();
        }

        // ---- S = Q K^T  (16 x 64 per warp) ----
        float s[8][4];
        #pragma unroll
        for (int nt = 0; nt < 8; nt++)
            #pragma unroll
            for (int i = 0; i < 4; i++) s[nt][i] = 0.f;

        #pragma unroll
        for (int kd = 0; kd < 8; kd++) {
            #pragma unroll
            for (int nt = 0; nt < 8; nt++) {
                uint32_t bf[2];
                const float* p = &Ks[(nt * 8 + g) * AT_KS + kd * 8 + t4];
                bf[0] = __float_as_uint(p[0]);
                bf[1] = __float_as_uint(p[4]);
                mma_tf32(s[nt], qf[kd], bf);
            }
        }

        // ---- scale + key bias + causal mask ----
        const int key0 = kt * 64;
        const bool need_mask = (kt >= 2 * qt);
        #pragma unroll
        for (int nt = 0; nt < 8; nt++) {
            const int c0 = key0 + nt * 8 + 2 * t4;
            const int c1 = c0 + 1;
            s[nt][0] = s[nt][0] * 0.125f + 0.01f * (float)c0;
            s[nt][1] = s[nt][1] * 0.125f + 0.01f * (float)c1;
            s[nt][2] = s[nt][2] * 0.125f + 0.01f * (float)c0;
            s[nt][3] = s[nt][3] * 0.125f + 0.01f * (float)c1;
            if (need_mask) {
                if (c0 > grow0) s[nt][0] = -1e30f;
                if (c1 > grow0) s[nt][1] = -1e30f;
                if (c0 > grow1) s[nt][2] = -1e30f;
                if (c1 > grow1) s[nt][3] = -1e30f;
            }
        }

        // ---- online softmax (rows g / g+8 live in t4 quad) ----
        float mx0 = -1e30f, mx1 = -1e30f;
        #pragma unroll
        for (int nt = 0; nt < 8; nt++) {
            mx0 = fmaxf(mx0, fmaxf(s[nt][0], s[nt][1]));
            mx1 = fmaxf(mx1, fmaxf(s[nt][2], s[nt][3]));
        }
        mx0 = fmaxf(mx0, __shfl_xor_sync(0xffffffffu, mx0, 1));
        mx0 = fmaxf(mx0, __shfl_xor_sync(0xffffffffu, mx0, 2));
        mx1 = fmaxf(mx1, __shfl_xor_sync(0xffffffffu, mx1, 1));
        mx1 = fmaxf(mx1, __shfl_xor_sync(0xffffffffu, mx1, 2));
        const float mn0 = fmaxf(m0, mx0);
        const float mn1 = fmaxf(m1, mx1);

        float sum0 = 0.f, sum1 = 0.f;
        #pragma unroll
        for (int nt = 0; nt < 8; nt++) {
            s[nt][0] = __expf(s[nt][0] - mn0);
            s[nt][1] = __expf(s[nt][1] - mn0);
            s[nt][2] = __expf(s[nt][2] - mn1);
            s[nt][3] = __expf(s[nt][3] - mn1);
            sum0 += s[nt][0] + s[nt][1];
            sum1 += s[nt][2] + s[nt][3];
        }
        sum0 += __shfl_xor_sync(0xffffffffu, sum0, 1);
        sum0 += __shfl_xor_sync(0xffffffffu, sum0, 2);
        sum1 += __shfl_xor_sync(0xffffffffu, sum1, 1);
        sum1 += __shfl_xor_sync(0xffffffffu, sum1, 2);

        const float corr0 = __expf(m0 - mn0);
        const float corr1 = __expf(m1 - mn1);
        l0 = l0 * corr0 + sum0;
        l1 = l1 * corr1 + sum1;
        m0 = mn0; m1 = mn1;
        #pragma unroll
        for (int nt = 0; nt < 8; nt++) {
            oa[nt][0] *= corr0; oa[nt][1] *= corr0;
            oa[nt][2] *= corr1; oa[nt][3] *= corr1;
        }

        // ---- stage P to smem ----
        {
            const int pr0 = warp * 16 + g;
            #pragma unroll
            for (int nt = 0; nt < 8; nt++) {
                const int c = nt * 8 + 2 * t4;
                *reinterpret_cast<float2*>(&Ps[pr0 * AT_PS + c])       = make_float2(s[nt][0], s[nt][1]);
                *reinterpret_cast<float2*>(&Ps[(pr0 + 8) * AT_PS + c]) = make_float2(s[nt][2], s[nt][3]);
            }
        }
        __syncthreads();

        // ---- O += P V  (k over 64 keys) ----
        const int pr0 = warp * 16 + g;
        #pragma unroll
        for (int kd = 0; kd < 8; kd++) {
            uint32_t pa[4];
            pa[0] = __float_as_uint(Ps[pr0 * AT_PS + kd * 8 + t4]);
            pa[1] = __float_as_uint(Ps[(pr0 + 8) * AT_PS + kd * 8 + t4]);
            pa[2] = __float_as_uint(Ps[pr0 * AT_PS + kd * 8 + t4 + 4]);
            pa[3] = __float_as_uint(Ps[(pr0 + 8) * AT_PS + kd * 8 + t4 + 4]);
            #pragma unroll
            for (int nt = 0; nt < 8; nt++) {
                uint32_t bf[2];
                bf[0] = __float_as_uint(Vs[(kd * 8 + t4) * AT_VS + nt * 8 + g]);
                bf[1] = __float_as_uint(Vs[(kd * 8 + t4 + 4) * AT_VS + nt * 8 + g]);
                mma_tf32(oa[nt], pa, bf);
            }
        }
    }

    // ---- normalize + write ----
    const float inv0 = 1.f / l0;
    const float inv1 = 1.f / l1;
    float* og = O + base;
    #pragma unroll
    for (int nt = 0; nt < 8; nt++) {
        const int c = nt * 8 + 2 * t4;
        *reinterpret_cast<float2*>(&og[(size_t)grow0 * DD + c]) =
            make_float2(oa[nt][0] * inv0, oa[nt][1] * inv0);
        *reinterpret_cast<float2*>(&og[(size_t)grow1 * DD + c]) =
            make_float2(oa[nt][2] * inv1, oa[nt][3] * inv1);
    }
}

// ---------------- launch ----------------
extern "C" void kernel_launch(void* const* d_in, const int* in_sizes, int n_in,
                              void* d_out, int out_size)
{
    const float* x    = (const float*)d_in[0];
    const float* wq   = (const float*)d_in[2];
    const float* wk   = (const float*)d_in[3];
    const float* wv   = (const float*)d_in[4];
    const float* wo   = (const float*)d_in[5];
    const float* ln1g = (const float*)d_in[6];
    const float* ln1b = (const float*)d_in[7];
    const float* ln2g = (const float*)d_in[8];
    const float* ln2b = (const float*)d_in[9];
    const float* w1   = (const float*)d_in[10];
    const float* b1   = (const float*)d_in[11];
    const float* wg   = (const float*)d_in[12];
    const float* w2   = (const float*)d_in[13];
    const float* b2   = (const float*)d_in[14];
    float* out = (float*)d_out;

    float *p_ln1, *p_q, *p_k, *p_v, *p_attn, *p_h, *p_ln2, *p_gate, *p_f;
    cudaGetSymbolAddress((void**)&p_ln1,  g_ln1);
    cudaGetSymbolAddress((void**)&p_q,    g_q);
    cudaGetSymbolAddress((void**)&p_k,    g_k);
    cudaGetSymbolAddress((void**)&p_v,    g_v);
    cudaGetSymbolAddress((void**)&p_attn, g_attn);
    cudaGetSymbolAddress((void**)&p_h,    g_h);
    cudaGetSymbolAddress((void**)&p_ln2,  g_ln2);
    cudaGetSymbolAddress((void**)&p_gate, g_gate);
    cudaGetSymbolAddress((void**)&p_f,    g_f);

    cudaFuncSetAttribute(attn_mma, cudaFuncAttributeMaxDynamicSharedMemorySize,
                         ATTN_SMEM_BYTES);

    // 1) ln1
    ln_kernel<<<NROWS, 256>>>(x, ln1g, ln1b, p_ln1);

    // 2) Q, K, V projections
    dim3 gQKV(DD / 128, NROWS / 128);
    mma_gemm_nt<<<gQKV, 256>>>(p_ln1, wq, p_q, NROWS, DD, DD, nullptr, nullptr, nullptr, EP_NONE);
    mma_gemm_nt<<<gQKV, 256>>>(p_ln1, wk, p_k, NROWS, DD, DD, nullptr, nullptr, nullptr, EP_NONE);
    mma_gemm_nt<<<gQKV, 256>>>(p_ln1, wv, p_v, NROWS, DD, DD, nullptr, nullptr, nullptr, EP_NONE);

    // 3) causal flash attention (tensor cores)
    dim3 gAttn(LL / 128, BB * HH);
    attn_mma<<<gAttn, 256, ATTN_SMEM_BYTES>>>(p_q, p_k, p_v, p_attn);

    // 4) output projection + residual -> h
    mma_gemm_nt<<<gQKV, 256>>>(p_attn, wo, p_h, NROWS, DD, DD, nullptr, x, nullptr, EP_RES);

    // 5) ln2
    ln_kernel<<<NROWS, 256>>>(p_h, ln2g, ln2b, p_ln2);

    // 6) gate = ln2 @ wg^T
    dim3 gFFN(HIDD / 128, NROWS / 128);
    mma_gemm_nt<<<gFFN, 256>>>(p_ln2, wg, p_gate, NROWS, HIDD, DD, nullptr, nullptr, nullptr, EP_NONE);

    // 7) f = silu(ln2 @ w1^T + b1) * gate
    mma_gemm_nt<<<gFFN, 256>>>(p_ln2, w1, p_f, NROWS, HIDD, DD, b1, nullptr, p_gate, EP_SILU_MUL);

    // 8) out = f @ w2^T + b2 + h
    dim3 gOut(DD / 128, NROWS / 128);
    mma_gemm_nt<<<gOut, 256>>>(p_f, w2, out, NROWS, DD, HIDD, b2, p_h, nullptr, EP_BIAS_RES);
}

// round 5
// speedup vs baseline: 3.8422x; 1.1063x over previous
#include <cuda_runtime.h>
#include <math.h>
#include <stdint.h>

#define BB 2
#define LL 2048
#define DD 1024
#define HH 16
#define HDIM 64
#define HIDD 4096
#define NROWS (BB*LL)   // 4096

// ---------------- scratch (static device globals; no allocation) ----------------
__device__ float g_ln1 [NROWS*DD];
__device__ float g_q   [NROWS*DD];
__device__ float g_k   [NROWS*DD];
__device__ float g_v   [NROWS*DD];
__device__ float g_attn[NROWS*DD];
__device__ float g_h   [NROWS*DD];
__device__ float g_ln2 [NROWS*DD];
__device__ float g_gate[(size_t)NROWS*HIDD];
__device__ float g_f   [(size_t)NROWS*HIDD];
__device__ float g_wbuf[16*1024*1024];   // tf32-RN-rounded weights

// ---------------- PTX helpers ----------------
__device__ __forceinline__ void cp16(uint32_t saddr, const float* gaddr) {
    asm volatile("cp.async.cg.shared.global [%0], [%1], 16;" :: "r"(saddr), "l"(gaddr));
}
__device__ __forceinline__ float tf32r(float f) {
    uint32_t u;
    asm("cvt.rna.tf32.f32 %0, %1;" : "=r"(u) : "f"(f));
    return __uint_as_float(u);
}
__device__ __forceinline__ void mma_tf32(float c[4],
                                         const uint32_t a[4], const uint32_t b[2]) {
    asm volatile(
        "mma.sync.aligned.m16n8k8.row.col.f32.tf32.tf32.f32 "
        "{%0,%1,%2,%3}, {%4,%5,%6,%7}, {%8,%9}, {%0,%1,%2,%3};"
        : "+f"(c[0]), "+f"(c[1]), "+f"(c[2]), "+f"(c[3])
        : "r"(a[0]), "r"(a[1]), "r"(a[2]), "r"(a[3]), "r"(b[0]), "r"(b[1]));
}

// ---------------- weight tf32-RN rounding ----------------
__global__ __launch_bounds__(256) void round_w(const float* __restrict__ in,
                                               float* __restrict__ outp, int n4)
{
    const int i = blockIdx.x * 256 + threadIdx.x;
    if (i < n4) {
        float4 v = reinterpret_cast<const float4*>(in)[i];
        v.x = tf32r(v.x); v.y = tf32r(v.y); v.z = tf32r(v.z); v.w = tf32r(v.w);
        reinterpret_cast<float4*>(outp)[i] = v;
    }
}

// ---------------- LayerNorm (output tf32-RN rounded; feeds GEMM A only) ----------------
__global__ __launch_bounds__(256) void ln_kernel(const float* __restrict__ x,
                                                 const float* __restrict__ gamma,
                                                 const float* __restrict__ beta,
                                                 float* __restrict__ y)
{
    const int row = blockIdx.x;
    const int tid = threadIdx.x;
    const float4 v = reinterpret_cast<const float4*>(x + (size_t)row * DD)[tid];
    float s = v.x + v.y + v.z + v.w;
    float q = v.x*v.x + v.y*v.y + v.z*v.z + v.w*v.w;
    #pragma unroll
    for (int o = 16; o >= 1; o >>= 1) {
        s += __shfl_xor_sync(0xffffffffu, s, o);
        q += __shfl_xor_sync(0xffffffffu, q, o);
    }
    __shared__ float ss[8], sq[8];
    __shared__ float stats[2];
    const int wid = tid >> 5;
    if ((tid & 31) == 0) { ss[wid] = s; sq[wid] = q; }
    __syncthreads();
    if (tid == 0) {
        float ts = 0.f, tq = 0.f;
        #pragma unroll
        for (int i = 0; i < 8; i++) { ts += ss[i]; tq += sq[i]; }
        float mu  = ts * (1.0f / DD);
        float var = tq * (1.0f / DD) - mu * mu;
        stats[0] = mu;
        stats[1] = rsqrtf(var + 1e-5f);
    }
    __syncthreads();
    const float mu = stats[0], rs = stats[1];
    const float4 g4 = reinterpret_cast<const float4*>(gamma)[tid];
    const float4 b4 = reinterpret_cast<const float4*>(beta)[tid];
    float4 o;
    o.x = tf32r((v.x - mu) * rs * g4.x + b4.x);
    o.y = tf32r((v.y - mu) * rs * g4.y + b4.y);
    o.z = tf32r((v.z - mu) * rs * g4.z + b4.z);
    o.w = tf32r((v.w - mu) * rs * g4.w + b4.w);
    reinterpret_cast<float4*>(y + (size_t)row * DD)[tid] = o;
}

// ---------------- TF32 mma.sync GEMM (NT), BK=32, 3-stage cp.async pipeline ----------------
#define EP_NONE     0
#define EP_RES      1
#define EP_SILU_MUL 2
#define EP_BIAS_RES 3
#define EP_ROUND    4

#define GBK  32
#define GSTR 36                         // 32 + 4 pad: banks (4*row + k) mod 32 conflict-free
#define STG_FLOATS (128 * GSTR)         // 4608 floats = 18432 B per operand per stage
#define N_STG 3
#define GEMM_SMEM_BYTES (N_STG * 2 * STG_FLOATS * 4)   // 110592

__global__ __launch_bounds__(256, 2) void mma_gemm_nt(
    const float* __restrict__ A, const float* __restrict__ W,
    float* __restrict__ C, int M, int N, int K,
    const float* __restrict__ bias, const float* __restrict__ res,
    const float* __restrict__ mul, int mode)
{
    extern __shared__ float smf[];
    float* As = smf;                          // [N_STG][128*GSTR]
    float* Bs = smf + N_STG * STG_FLOATS;     // [N_STG][128*GSTR]

    const int tid  = threadIdx.x;
    const int lane = tid & 31;
    const int warp = tid >> 5;
    const int g    = lane >> 2;
    const int t4   = lane & 3;
    const int wm   = (warp >> 2) * 64;
    const int wn   = (warp & 3)  * 32;
    const int row0 = blockIdx.y * 128;
    const int col0 = blockIdx.x * 128;

    // loader mapping: 128 rows x 32 cols per operand per stage; 4 float4/thread each
    const int lr  = tid >> 3;            // 0..31
    const int lc4 = (tid & 7) << 2;      // 0,4,...,28

    const float* Ag = A + (size_t)(row0 + lr) * K + lc4;
    const float* Wg = W + (size_t)(col0 + lr) * K + lc4;
    const uint32_t sA = (uint32_t)__cvta_generic_to_shared(&As[lr * GSTR + lc4]);
    const uint32_t sB = (uint32_t)__cvta_generic_to_shared(&Bs[lr * GSTR + lc4]);
    const uint32_t stgB = (uint32_t)(STG_FLOATS * 4);
    const uint32_t rowB = (uint32_t)(32 * GSTR * 4);

    float acc[4][4][4];
    #pragma unroll
    for (int mt = 0; mt < 4; mt++)
        #pragma unroll
        for (int nt = 0; nt < 4; nt++)
            #pragma unroll
            for (int i = 0; i < 4; i++) acc[mt][nt][i] = 0.f;

    const int nk = K / GBK;

    // prologue: stages 0,1
    #pragma unroll
    for (int st = 0; st < 2; st++) {
        const int ko = st * GBK;
        const uint32_t so = (uint32_t)st * stgB;
        #pragma unroll
        for (int i = 0; i < 4; i++) {
            cp16(sA + so + (uint32_t)i * rowB, Ag + (size_t)(i * 32) * K + ko);
            cp16(sB + so + (uint32_t)i * rowB, Wg + (size_t)(i * 32) * K + ko);
        }
        asm volatile("cp.async.commit_group;");
    }

    int sc = 0;   // compute stage index (kt % 3)
    for (int kt = 0; kt < nk; kt++) {
        asm volatile("cp.async.wait_group 1;");
        __syncthreads();

        // issue load for kt+2 into stage (kt+2)%3 == (sc+2)%3
        if (kt + 2 < nk) {
            const int ko = (kt + 2) * GBK;
            int sl = sc + 2; if (sl >= N_STG) sl -= N_STG;
            const uint32_t so = (uint32_t)sl * stgB;
            #pragma unroll
            for (int i = 0; i < 4; i++) {
                cp16(sA + so + (uint32_t)i * rowB, Ag + (size_t)(i * 32) * K + ko);
                cp16(sB + so + (uint32_t)i * rowB, Wg + (size_t)(i * 32) * K + ko);
            }
        }
        asm volatile("cp.async.commit_group;");

        const float* as = &As[sc * STG_FLOATS];
        const float* bs = &Bs[sc * STG_FLOATS];
        #pragma unroll
        for (int ks = 0; ks < 4; ks++) {
            const int kb = ks * 8;
            uint32_t af[4][4];
            uint32_t bf[4][2];
            #pragma unroll
            for (int mt = 0; mt < 4; mt++) {
                const float* p = &as[(wm + mt * 16 + g) * GSTR + kb + t4];
                af[mt][0] = __float_as_uint(p[0]);
                af[mt][1] = __float_as_uint(p[8 * GSTR]);
                af[mt][2] = __float_as_uint(p[4]);
                af[mt][3] = __float_as_uint(p[8 * GSTR + 4]);
            }
            #pragma unroll
            for (int nt = 0; nt < 4; nt++) {
                const float* p = &bs[(wn + nt * 8 + g) * GSTR + kb + t4];
                bf[nt][0] = __float_as_uint(p[0]);
                bf[nt][1] = __float_as_uint(p[4]);
            }
            #pragma unroll
            for (int mt = 0; mt < 4; mt++)
                #pragma unroll
                for (int nt = 0; nt < 4; nt++)
                    mma_tf32(acc[mt][nt], af[mt], bf[nt]);
        }

        if (++sc == N_STG) sc = 0;
    }

    // ---------------- epilogue ----------------
    #pragma unroll
    for (int mt = 0; mt < 4; mt++) {
        #pragma unroll
        for (int nt = 0; nt < 4; nt++) {
            const int r = row0 + wm + mt * 16 + g;
            const int c = col0 + wn + nt * 8 + 2 * t4;
            const size_t i0 = (size_t)r * N + c;
            const size_t i1 = i0 + (size_t)8 * N;
            float v00 = acc[mt][nt][0], v01 = acc[mt][nt][1];
            float v10 = acc[mt][nt][2], v11 = acc[mt][nt][3];

            if (mode == EP_RES) {
                const float2 r0v = *reinterpret_cast<const float2*>(&res[i0]);
                const float2 r1v = *reinterpret_cast<const float2*>(&res[i1]);
                v00 += r0v.x; v01 += r0v.y; v10 += r1v.x; v11 += r1v.y;
            } else if (mode == EP_SILU_MUL) {
                const float2 bb  = *reinterpret_cast<const float2*>(&bias[c]);
                const float2 m0v = *reinterpret_cast<const float2*>(&mul[i0]);
                const float2 m1v = *reinterpret_cast<const float2*>(&mul[i1]);
                float x;
                x = v00 + bb.x; v00 = tf32r(x / (1.f + __expf(-x)) * m0v.x);
                x = v01 + bb.y; v01 = tf32r(x / (1.f + __expf(-x)) * m0v.y);
                x = v10 + bb.x; v10 = tf32r(x / (1.f + __expf(-x)) * m1v.x);
                x = v11 + bb.y; v11 = tf32r(x / (1.f + __expf(-x)) * m1v.y);
            } else if (mode == EP_BIAS_RES) {
                const float2 bb  = *reinterpret_cast<const float2*>(&bias[c]);
                const float2 r0v = *reinterpret_cast<const float2*>(&res[i0]);
                const float2 r1v = *reinterpret_cast<const float2*>(&res[i1]);
                v00 += bb.x + r0v.x; v01 += bb.y + r0v.y;
                v10 += bb.x + r1v.x; v11 += bb.y + r1v.y;
            } else if (mode == EP_ROUND) {
                v00 = tf32r(v00); v01 = tf32r(v01);
                v10 = tf32r(v10); v11 = tf32r(v11);
            }
            *reinterpret_cast<float2*>(&C[i0]) = make_float2(v00, v01);
            *reinterpret_cast<float2*>(&C[i1]) = make_float2(v10, v11);
        }
    }
}

// ---------------- Tensor-core causal flash attention (HMMA tf32) ----------------
#define AT_KS 68
#define AT_VS 72
#define AT_PS 68
#define ATTN_SMEM_BYTES ((64*AT_KS + 64*AT_VS + 128*AT_PS) * 4)

__global__ __launch_bounds__(256) void attn_mma(
    const float* __restrict__ Q, const float* __restrict__ Kx,
    const float* __restrict__ V, float* __restrict__ O)
{
    extern __shared__ float sm[];
    float* Ks = sm;
    float* Vs = Ks + 64 * AT_KS;
    float* Ps = Vs + 64 * AT_VS;

    const int tid  = threadIdx.x;
    const int lane = tid & 31;
    const int warp = tid >> 5;
    const int g    = lane >> 2;
    const int t4   = lane & 3;

    const int qt = blockIdx.x;
    const int bh = blockIdx.y;
    const int b  = bh >> 4, h = bh & 15;
    const size_t base = ((size_t)b * LL) * DD + (size_t)h * HDIM;

    const int qrow0 = qt * 128 + warp * 16;
    const int grow0 = qrow0 + g;
    const int grow1 = grow0 + 8;

    uint32_t qf[8][4];
    {
        const float* qg = Q + base;
        #pragma unroll
        for (int kd = 0; kd < 8; kd++) {
            const int c = kd * 8 + t4;
            qf[kd][0] = __float_as_uint(qg[(size_t)grow0 * DD + c]);
            qf[kd][1] = __float_as_uint(qg[(size_t)grow1 * DD + c]);
            qf[kd][2] = __float_as_uint(qg[(size_t)grow0 * DD + c + 4]);
            qf[kd][3] = __float_as_uint(qg[(size_t)grow1 * DD + c + 4]);
        }
    }

    float oa[8][4];
    #pragma unroll
    for (int nt = 0; nt < 8; nt++)
        #pragma unroll
        for (int i = 0; i < 4; i++) oa[nt][i] = 0.f;
    float m0 = -1e30f, m1 = -1e30f, l0 = 0.f, l1 = 0.f;

    const uint32_t sKs = (uint32_t)__cvta_generic_to_shared(Ks);
    const uint32_t sVs = (uint32_t)__cvta_generic_to_shared(Vs);

    const int ktmax = 2 * qt + 1;
    for (int kt = 0; kt <= ktmax; kt++) {
        __syncthreads();
        {
            const float* kg = Kx + base + (size_t)(kt * 64) * DD;
            const float* vg = V  + base + (size_t)(kt * 64) * DD;
            #pragma unroll
            for (int i = 0; i < 4; i++) {
                const int idx = tid + i * 256;
                const int r = idx >> 4;
                const int c = (idx & 15) << 2;
                cp16(sKs + (uint32_t)(r * AT_KS + c) * 4, kg + (size_t)r * DD + c);
                cp16(sVs + (uint32_t)(r * AT_VS + c) * 4, vg + (size_t)r * DD + c);
            }
            asm volatile("cp.async.commit_group;");
            asm volatile("cp.async.wait_group 0;");
            __syncthreads();
        }

        float s[8][4];
        #pragma unroll
        for (int nt = 0; nt < 8; nt++)
            #pragma unroll
            for (int i = 0; i < 4; i++) s[nt][i] = 0.f;

        #pragma unroll
        for (int kd = 0; kd < 8; kd++) {
            #pragma unroll
            for (int nt = 0; nt < 8; nt++) {
                uint32_t bf[2];
                const float* p = &Ks[(nt * 8 + g) * AT_KS + kd * 8 + t4];
                bf[0] = __float_as_uint(p[0]);
                bf[1] = __float_as_uint(p[4]);
                mma_tf32(s[nt], qf[kd], bf);
            }
        }

        const int key0 = kt * 64;
        const bool need_mask = (kt >= 2 * qt);
        #pragma unroll
        for (int nt = 0; nt < 8; nt++) {
            const int c0 = key0 + nt * 8 + 2 * t4;
            const int c1 = c0 + 1;
            s[nt][0] = s[nt][0] * 0.125f + 0.01f * (float)c0;
            s[nt][1] = s[nt][1] * 0.125f + 0.01f * (float)c1;
            s[nt][2] = s[nt][2] * 0.125f + 0.01f * (float)c0;
            s[nt][3] = s[nt][3] * 0.125f + 0.01f * (float)c1;
            if (need_mask) {
                if (c0 > grow0) s[nt][0] = -1e30f;
                if (c1 > grow0) s[nt][1] = -1e30f;
                if (c0 > grow1) s[nt][2] = -1e30f;
                if (c1 > grow1) s[nt][3] = -1e30f;
            }
        }

        float mx0 = -1e30f, mx1 = -1e30f;
        #pragma unroll
        for (int nt = 0; nt < 8; nt++) {
            mx0 = fmaxf(mx0, fmaxf(s[nt][0], s[nt][1]));
            mx1 = fmaxf(mx1, fmaxf(s[nt][2], s[nt][3]));
        }
        mx0 = fmaxf(mx0, __shfl_xor_sync(0xffffffffu, mx0, 1));
        mx0 = fmaxf(mx0, __shfl_xor_sync(0xffffffffu, mx0, 2));
        mx1 = fmaxf(mx1, __shfl_xor_sync(0xffffffffu, mx1, 1));
        mx1 = fmaxf(mx1, __shfl_xor_sync(0xffffffffu, mx1, 2));
        const float mn0 = fmaxf(m0, mx0);
        const float mn1 = fmaxf(m1, mx1);

        float sum0 = 0.f, sum1 = 0.f;
        #pragma unroll
        for (int nt = 0; nt < 8; nt++) {
            s[nt][0] = __expf(s[nt][0] - mn0);
            s[nt][1] = __expf(s[nt][1] - mn0);
            s[nt][2] = __expf(s[nt][2] - mn1);
            s[nt][3] = __expf(s[nt][3] - mn1);
            sum0 += s[nt][0] + s[nt][1];
            sum1 += s[nt][2] + s[nt][3];
        }
        sum0 += __shfl_xor_sync(0xffffffffu, sum0, 1);
        sum0 += __shfl_xor_sync(0xffffffffu, sum0, 2);
        sum1 += __shfl_xor_sync(0xffffffffu, sum1, 1);
        sum1 += __shfl_xor_sync(0xffffffffu, sum1, 2);

        const float corr0 = __expf(m0 - mn0);
        const float corr1 = __expf(m1 - mn1);
        l0 = l0 * corr0 + sum0;
        l1 = l1 * corr1 + sum1;
        m0 = mn0; m1 = mn1;
        #pragma unroll
        for (int nt = 0; nt < 8; nt++) {
            oa[nt][0] *= corr0; oa[nt][1] *= corr0;
            oa[nt][2] *= corr1; oa[nt][3] *= corr1;
        }

        {
            const int pr0 = warp * 16 + g;
            #pragma unroll
            for (int nt = 0; nt < 8; nt++) {
                const int c = nt * 8 + 2 * t4;
                *reinterpret_cast<float2*>(&Ps[pr0 * AT_PS + c])       = make_float2(s[nt][0], s[nt][1]);
                *reinterpret_cast<float2*>(&Ps[(pr0 + 8) * AT_PS + c]) = make_float2(s[nt][2], s[nt][3]);
            }
        }
        __syncthreads();

        const int pr0 = warp * 16 + g;
        #pragma unroll
        for (int kd = 0; kd < 8; kd++) {
            uint32_t pa[4];
            pa[0] = __float_as_uint(Ps[pr0 * AT_PS + kd * 8 + t4]);
            pa[1] = __float_as_uint(Ps[(pr0 + 8) * AT_PS + kd * 8 + t4]);
            pa[2] = __float_as_uint(Ps[pr0 * AT_PS + kd * 8 + t4 + 4]);
            pa[3] = __float_as_uint(Ps[(pr0 + 8) * AT_PS + kd * 8 + t4 + 4]);
            #pragma unroll
            for (int nt = 0; nt < 8; nt++) {
                uint32_t bf[2];
                bf[0] = __float_as_uint(Vs[(kd * 8 + t4) * AT_VS + nt * 8 + g]);
                bf[1] = __float_as_uint(Vs[(kd * 8 + t4 + 4) * AT_VS + nt * 8 + g]);
                mma_tf32(oa[nt], pa, bf);
            }
        }
    }

    const float inv0 = 1.f / l0;
    const float inv1 = 1.f / l1;
    float* og = O + base;
    #pragma unroll
    for (int nt = 0; nt < 8; nt++) {
        const int c = nt * 8 + 2 * t4;
        *reinterpret_cast<float2*>(&og[(size_t)grow0 * DD + c]) =
            make_float2(tf32r(oa[nt][0] * inv0), tf32r(oa[nt][1] * inv0));
        *reinterpret_cast<float2*>(&og[(size_t)grow1 * DD + c]) =
            make_float2(tf32r(oa[nt][2] * inv1), tf32r(oa[nt][3] * inv1));
    }
}

// ---------------- launch ----------------
extern "C" void kernel_launch(void* const* d_in, const int* in_sizes, int n_in,
                              void* d_out, int out_size)
{
    const float* x    = (const float*)d_in[0];
    const float* wq   = (const float*)d_in[2];
    const float* wk   = (const float*)d_in[3];
    const float* wv   = (const float*)d_in[4];
    const float* wo   = (const float*)d_in[5];
    const float* ln1g = (const float*)d_in[6];
    const float* ln1b = (const float*)d_in[7];
    const float* ln2g = (const float*)d_in[8];
    const float* ln2b = (const float*)d_in[9];
    const float* w1   = (const float*)d_in[10];
    const float* b1   = (const float*)d_in[11];
    const float* wg   = (const float*)d_in[12];
    const float* w2   = (const float*)d_in[13];
    const float* b2   = (const float*)d_in[14];
    float* out = (float*)d_out;

    float *p_ln1, *p_q, *p_k, *p_v, *p_attn, *p_h, *p_ln2, *p_gate, *p_f, *p_wb;
    cudaGetSymbolAddress((void**)&p_ln1,  g_ln1);
    cudaGetSymbolAddress((void**)&p_q,    g_q);
    cudaGetSymbolAddress((void**)&p_k,    g_k);
    cudaGetSymbolAddress((void**)&p_v,    g_v);
    cudaGetSymbolAddress((void**)&p_attn, g_attn);
    cudaGetSymbolAddress((void**)&p_h,    g_h);
    cudaGetSymbolAddress((void**)&p_ln2,  g_ln2);
    cudaGetSymbolAddress((void**)&p_gate, g_gate);
    cudaGetSymbolAddress((void**)&p_f,    g_f);
    cudaGetSymbolAddress((void**)&p_wb,   g_wbuf);

    float* rwq = p_wb;
    float* rwk = p_wb + (size_t)1*1024*1024;
    float* rwv = p_wb + (size_t)2*1024*1024;
    float* rwo = p_wb + (size_t)3*1024*1024;
    float* rw1 = p_wb + (size_t)4*1024*1024;
    float* rwg = p_wb + (size_t)8*1024*1024;
    float* rw2 = p_wb + (size_t)12*1024*1024;

    cudaFuncSetAttribute(mma_gemm_nt, cudaFuncAttributeMaxDynamicSharedMemorySize,
                         GEMM_SMEM_BYTES);
    cudaFuncSetAttribute(attn_mma, cudaFuncAttributeMaxDynamicSharedMemorySize,
                         ATTN_SMEM_BYTES);

    // 0) round weights to tf32-RN (HW truncation then == round-to-nearest)
    const int n4_d  = DD*DD/4;
    const int n4_h  = HIDD*DD/4;
    round_w<<<(n4_d+255)/256, 256>>>(wq, rwq, n4_d);
    round_w<<<(n4_d+255)/256, 256>>>(wk, rwk, n4_d);
    round_w<<<(n4_d+255)/256, 256>>>(wv, rwv, n4_d);
    round_w<<<(n4_d+255)/256, 256>>>(wo, rwo, n4_d);
    round_w<<<(n4_h+255)/256, 256>>>(w1, rw1, n4_h);
    round_w<<<(n4_h+255)/256, 256>>>(wg, rwg, n4_h);
    round_w<<<(n4_h+255)/256, 256>>>(w2, rw2, n4_h);

    // 1) ln1
    ln_kernel<<<NROWS, 256>>>(x, ln1g, ln1b, p_ln1);

    // 2) Q, K, V projections
    dim3 gQKV(DD / 128, NROWS / 128);
    mma_gemm_nt<<<gQKV, 256, GEMM_SMEM_BYTES>>>(p_ln1, rwq, p_q, NROWS, DD, DD, nullptr, nullptr, nullptr, EP_ROUND);
    mma_gemm_nt<<<gQKV, 256, GEMM_SMEM_BYTES>>>(p_ln1, rwk, p_k, NROWS, DD, DD, nullptr, nullptr, nullptr, EP_ROUND);
    mma_gemm_nt<<<gQKV, 256, GEMM_SMEM_BYTES>>>(p_ln1, rwv, p_v, NROWS, DD, DD, nullptr, nullptr, nullptr, EP_ROUND);

    // 3) causal flash attention
    dim3 gAttn(LL / 128, BB * HH);
    attn_mma<<<gAttn, 256, ATTN_SMEM_BYTES>>>(p_q, p_k, p_v, p_attn);

    // 4) output projection + residual -> h
    mma_gemm_nt<<<gQKV, 256, GEMM_SMEM_BYTES>>>(p_attn, rwo, p_h, NROWS, DD, DD, nullptr, x, nullptr, EP_RES);

    // 5) ln2
    ln_kernel<<<NROWS, 256>>>(p_h, ln2g, ln2b, p_ln2);

    // 6) gate = ln2 @ wg^T
    dim3 gFFN(HIDD / 128, NROWS / 128);
    mma_gemm_nt<<<gFFN, 256, GEMM_SMEM_BYTES>>>(p_ln2, rwg, p_gate, NROWS, HIDD, DD, nullptr, nullptr, nullptr, EP_ROUND);

    // 7) f = silu(ln2 @ w1^T + b1) * gate
    mma_gemm_nt<<<gFFN, 256, GEMM_SMEM_BYTES>>>(p_ln2, rw1, p_f, NROWS, HIDD, DD, b1, nullptr, p_gate, EP_SILU_MUL);

    // 8) out = f @ w2^T + b2 + h
    dim3 gOut(DD / 128, NROWS / 128);
    mma_gemm_nt<<<gOut, 256, GEMM_SMEM_BYTES>>>(p_f, rw2, out, NROWS, DD, HIDD, b2, p_h, nullptr, EP_BIAS_RES);
}

// round 6
// speedup vs baseline: 3.9789x; 1.0356x over previous
#include <cuda_runtime.h>
#include <math.h>
#include <stdint.h>

#define BB 2
#define LL 2048
#define DD 1024
#define HH 16
#define HDIM 64
#define HIDD 4096
#define NROWS (BB*LL)   // 4096
#define QS 3072         // packed qkv row stride

// ---------------- scratch (static device globals; no allocation) ----------------
__device__ float g_ln1 [NROWS*DD];
__device__ float g_qkv [(size_t)NROWS*QS];
__device__ float g_attn[NROWS*DD];
__device__ float g_h   [NROWS*DD];
__device__ float g_ln2 [NROWS*DD];
__device__ float g_f   [(size_t)NROWS*HIDD];
__device__ float g_wbuf[16*1024*1024];   // tf32-RN-rounded weights

// ---------------- PTX helpers ----------------
__device__ __forceinline__ void cp16(uint32_t saddr, const float* gaddr) {
    asm volatile("cp.async.cg.shared.global [%0], [%1], 16;" :: "r"(saddr), "l"(gaddr));
}
__device__ __forceinline__ float tf32r(float f) {
    uint32_t u;
    asm("cvt.rna.tf32.f32 %0, %1;" : "=r"(u) : "f"(f));
    return __uint_as_float(u);
}
__device__ __forceinline__ void mma_tf32(float c[4],
                                         const uint32_t a[4], const uint32_t b[2]) {
    asm volatile(
        "mma.sync.aligned.m16n8k8.row.col.f32.tf32.tf32.f32 "
        "{%0,%1,%2,%3}, {%4,%5,%6,%7}, {%8,%9}, {%0,%1,%2,%3};"
        : "+f"(c[0]), "+f"(c[1]), "+f"(c[2]), "+f"(c[3])
        : "r"(a[0]), "r"(a[1]), "r"(a[2]), "r"(a[3]), "r"(b[0]), "r"(b[1]));
}

// ---------------- weight prep: tf32-RN round (+ optional row interleave) ----------------
__global__ __launch_bounds__(256) void round_w(const float* __restrict__ in,
                                               float* __restrict__ outp, int n4)
{
    const int i = blockIdx.x * 256 + threadIdx.x;
    if (i < n4) {
        float4 v = reinterpret_cast<const float4*>(in)[i];
        v.x = tf32r(v.x); v.y = tf32r(v.y); v.z = tf32r(v.z); v.w = tf32r(v.w);
        reinterpret_cast<float4*>(outp)[i] = v;
    }
}

// out rows: [2j] = w1[j], [2j+1] = wg[j]  (both tf32-RN rounded)
__global__ __launch_bounds__(256) void round_interleave(const float* __restrict__ w1,
                                                        const float* __restrict__ wg,
                                                        float* __restrict__ outp)
{
    const int t = blockIdx.x * 256 + threadIdx.x;   // over HIDD*(DD/4)
    if (t < HIDD * (DD/4)) {
        const int j  = t / (DD/4);
        const int k4 = t % (DD/4);
        float4 a = reinterpret_cast<const float4*>(w1)[t];
        float4 g = reinterpret_cast<const float4*>(wg)[t];
        a.x = tf32r(a.x); a.y = tf32r(a.y); a.z = tf32r(a.z); a.w = tf32r(a.w);
        g.x = tf32r(g.x); g.y = tf32r(g.y); g.z = tf32r(g.z); g.w = tf32r(g.w);
        reinterpret_cast<float4*>(outp)[(size_t)(2*j)     * (DD/4) + k4] = a;
        reinterpret_cast<float4*>(outp)[(size_t)(2*j + 1) * (DD/4) + k4] = g;
    }
}

// ---------------- LayerNorm (tf32-RN rounded output; feeds GEMM A) ----------------
__global__ __launch_bounds__(256) void ln_kernel(const float* __restrict__ x,
                                                 const float* __restrict__ gamma,
                                                 const float* __restrict__ beta,
                                                 float* __restrict__ y)
{
    const int row = blockIdx.x;
    const int tid = threadIdx.x;
    const float4 v = reinterpret_cast<const float4*>(x + (size_t)row * DD)[tid];
    float s = v.x + v.y + v.z + v.w;
    float q = v.x*v.x + v.y*v.y + v.z*v.z + v.w*v.w;
    #pragma unroll
    for (int o = 16; o >= 1; o >>= 1) {
        s += __shfl_xor_sync(0xffffffffu, s, o);
        q += __shfl_xor_sync(0xffffffffu, q, o);
    }
    __shared__ float ss[8], sq[8];
    __shared__ float stats[2];
    const int wid = tid >> 5;
    if ((tid & 31) == 0) { ss[wid] = s; sq[wid] = q; }
    __syncthreads();
    if (tid == 0) {
        float ts = 0.f, tq = 0.f;
        #pragma unroll
        for (int i = 0; i < 8; i++) { ts += ss[i]; tq += sq[i]; }
        float mu  = ts * (1.0f / DD);
        float var = tq * (1.0f / DD) - mu * mu;
        stats[0] = mu;
        stats[1] = rsqrtf(var + 1e-5f);
    }
    __syncthreads();
    const float mu = stats[0], rs = stats[1];
    const float4 g4 = reinterpret_cast<const float4*>(gamma)[tid];
    const float4 b4 = reinterpret_cast<const float4*>(beta)[tid];
    float4 o;
    o.x = tf32r((v.x - mu) * rs * g4.x + b4.x);
    o.y = tf32r((v.y - mu) * rs * g4.y + b4.y);
    o.z = tf32r((v.z - mu) * rs * g4.z + b4.z);
    o.w = tf32r((v.w - mu) * rs * g4.w + b4.w);
    reinterpret_cast<float4*>(y + (size_t)row * DD)[tid] = o;
}

// ---------------- TF32 mma.sync GEMM (NT), BK=32, 3-stage cp.async pipeline ----------------
#define EP_ROUND     0
#define EP_RES       1
#define EP_SILU_PAIR 2   // interleaved w1/wg: C[r][c/2] = silu(even+b1)*odd
#define EP_BIAS_RES  3

#define GBK  32
#define GSTR 36
#define STG_FLOATS (128 * GSTR)
#define N_STG 3
#define GEMM_SMEM_BYTES (N_STG * 2 * STG_FLOATS * 4)   // 110592

__global__ __launch_bounds__(256, 2) void mma_gemm_nt(
    const float* __restrict__ A, const float* __restrict__ W,
    float* __restrict__ C, int M, int N, int K,
    const float* __restrict__ bias, const float* __restrict__ res, int mode)
{
    extern __shared__ float smf[];
    float* As = smf;
    float* Bs = smf + N_STG * STG_FLOATS;

    const int tid  = threadIdx.x;
    const int lane = tid & 31;
    const int warp = tid >> 5;
    const int g    = lane >> 2;
    const int t4   = lane & 3;
    const int wm   = (warp >> 2) * 64;
    const int wn   = (warp & 3)  * 32;
    const int row0 = blockIdx.y * 128;
    const int col0 = blockIdx.x * 128;

    const int lr  = tid >> 3;
    const int lc4 = (tid & 7) << 2;

    const float* Ag = A + (size_t)(row0 + lr) * K + lc4;
    const float* Wg = W + (size_t)(col0 + lr) * K + lc4;
    const uint32_t sA = (uint32_t)__cvta_generic_to_shared(&As[lr * GSTR + lc4]);
    const uint32_t sB = (uint32_t)__cvta_generic_to_shared(&Bs[lr * GSTR + lc4]);
    const uint32_t stgB = (uint32_t)(STG_FLOATS * 4);
    const uint32_t rowB = (uint32_t)(32 * GSTR * 4);

    float acc[4][4][4];
    #pragma unroll
    for (int mt = 0; mt < 4; mt++)
        #pragma unroll
        for (int nt = 0; nt < 4; nt++)
            #pragma unroll
            for (int i = 0; i < 4; i++) acc[mt][nt][i] = 0.f;

    const int nk = K / GBK;

    #pragma unroll
    for (int st = 0; st < 2; st++) {
        const int ko = st * GBK;
        const uint32_t so = (uint32_t)st * stgB;
        #pragma unroll
        for (int i = 0; i < 4; i++) {
            cp16(sA + so + (uint32_t)i * rowB, Ag + (size_t)(i * 32) * K + ko);
            cp16(sB + so + (uint32_t)i * rowB, Wg + (size_t)(i * 32) * K + ko);
        }
        asm volatile("cp.async.commit_group;");
    }

    int sc = 0;
    for (int kt = 0; kt < nk; kt++) {
        asm volatile("cp.async.wait_group 1;");
        __syncthreads();

        if (kt + 2 < nk) {
            const int ko = (kt + 2) * GBK;
            int sl = sc + 2; if (sl >= N_STG) sl -= N_STG;
            const uint32_t so = (uint32_t)sl * stgB;
            #pragma unroll
            for (int i = 0; i < 4; i++) {
                cp16(sA + so + (uint32_t)i * rowB, Ag + (size_t)(i * 32) * K + ko);
                cp16(sB + so + (uint32_t)i * rowB, Wg + (size_t)(i * 32) * K + ko);
            }
        }
        asm volatile("cp.async.commit_group;");

        const float* as = &As[sc * STG_FLOATS];
        const float* bs = &Bs[sc * STG_FLOATS];
        #pragma unroll
        for (int ks = 0; ks < 4; ks++) {
            const int kb = ks * 8;
            uint32_t af[4][4];
            uint32_t bf[4][2];
            #pragma unroll
            for (int mt = 0; mt < 4; mt++) {
                const float* p = &as[(wm + mt * 16 + g) * GSTR + kb + t4];
                af[mt][0] = __float_as_uint(p[0]);
                af[mt][1] = __float_as_uint(p[8 * GSTR]);
                af[mt][2] = __float_as_uint(p[4]);
                af[mt][3] = __float_as_uint(p[8 * GSTR + 4]);
            }
            #pragma unroll
            for (int nt = 0; nt < 4; nt++) {
                const float* p = &bs[(wn + nt * 8 + g) * GSTR + kb + t4];
                bf[nt][0] = __float_as_uint(p[0]);
                bf[nt][1] = __float_as_uint(p[4]);
            }
            #pragma unroll
            for (int mt = 0; mt < 4; mt++)
                #pragma unroll
                for (int nt = 0; nt < 4; nt++)
                    mma_tf32(acc[mt][nt], af[mt], bf[nt]);
        }

        if (++sc == N_STG) sc = 0;
    }

    // ---------------- epilogue ----------------
    #pragma unroll
    for (int mt = 0; mt < 4; mt++) {
        #pragma unroll
        for (int nt = 0; nt < 4; nt++) {
            const int r = row0 + wm + mt * 16 + g;
            const int c = col0 + wn + nt * 8 + 2 * t4;
            float v00 = acc[mt][nt][0], v01 = acc[mt][nt][1];
            float v10 = acc[mt][nt][2], v11 = acc[mt][nt][3];

            if (mode == EP_SILU_PAIR) {
                // cols (c, c+1) = (a_j, g_j), j = c/2; f[r][j] = silu(a+b1[j])*g
                const int jn = N >> 1;
                const int j  = ((col0 + wn + nt * 8) >> 1) + t4;
                const float bb = bias[j];
                float x0 = v00 + bb;
                float x1 = v10 + bb;
                const float f0 = tf32r(x0 / (1.f + __expf(-x0)) * v01);
                const float f1 = tf32r(x1 / (1.f + __expf(-x1)) * v11);
                C[(size_t)r * jn + j]       = f0;
                C[(size_t)(r + 8) * jn + j] = f1;
            } else {
                const size_t i0 = (size_t)r * N + c;
                const size_t i1 = i0 + (size_t)8 * N;
                if (mode == EP_RES) {
                    const float2 r0v = *reinterpret_cast<const float2*>(&res[i0]);
                    const float2 r1v = *reinterpret_cast<const float2*>(&res[i1]);
                    v00 += r0v.x; v01 += r0v.y; v10 += r1v.x; v11 += r1v.y;
                } else if (mode == EP_BIAS_RES) {
                    const float2 bb  = *reinterpret_cast<const float2*>(&bias[c]);
                    const float2 r0v = *reinterpret_cast<const float2*>(&res[i0]);
                    const float2 r1v = *reinterpret_cast<const float2*>(&res[i1]);
                    v00 += bb.x + r0v.x; v01 += bb.y + r0v.y;
                    v10 += bb.x + r1v.x; v11 += bb.y + r1v.y;
                } else { // EP_ROUND
                    v00 = tf32r(v00); v01 = tf32r(v01);
                    v10 = tf32r(v10); v11 = tf32r(v11);
                }
                *reinterpret_cast<float2*>(&C[i0]) = make_float2(v00, v01);
                *reinterpret_cast<float2*>(&C[i1]) = make_float2(v10, v11);
            }
        }
    }
}

// ---------------- Tensor-core causal flash attention, double-buffered K/V ----------------
#define AT_KS 68
#define AT_VS 72
#define AT_PS 68
#define KSTG (64*AT_KS)
#define VSTG (64*AT_VS)
#define ATTN_SMEM_BYTES ((2*KSTG + 2*VSTG + 128*AT_PS) * 4)   // 106496

__global__ __launch_bounds__(256, 2) void attn_mma(
    const float* __restrict__ QKV, float* __restrict__ O)
{
    extern __shared__ float sm[];
    float* Ks = sm;                        // [2][64][AT_KS]
    float* Vs = Ks + 2 * KSTG;             // [2][64][AT_VS]
    float* Ps = Vs + 2 * VSTG;             // [128][AT_PS]

    const int tid  = threadIdx.x;
    const int lane = tid & 31;
    const int warp = tid >> 5;
    const int g    = lane >> 2;
    const int t4   = lane & 3;

    const int qt = blockIdx.x;
    const int bh = blockIdx.y;
    const int b  = bh >> 4, h = bh & 15;
    const size_t qoff = (size_t)b * LL * QS + (size_t)h * HDIM;
    const float* qg = QKV + qoff;              // q columns
    const float* kg0 = QKV + qoff + DD;        // k columns
    const float* vg0 = QKV + qoff + 2 * DD;    // v columns

    const int qrow0 = qt * 128 + warp * 16;
    const int grow0 = qrow0 + g;
    const int grow1 = grow0 + 8;

    uint32_t qf[8][4];
    #pragma unroll
    for (int kd = 0; kd < 8; kd++) {
        const int c = kd * 8 + t4;
        qf[kd][0] = __float_as_uint(qg[(size_t)grow0 * QS + c]);
        qf[kd][1] = __float_as_uint(qg[(size_t)grow1 * QS + c]);
        qf[kd][2] = __float_as_uint(qg[(size_t)grow0 * QS + c + 4]);
        qf[kd][3] = __float_as_uint(qg[(size_t)grow1 * QS + c + 4]);
    }

    float oa[8][4];
    #pragma unroll
    for (int nt = 0; nt < 8; nt++)
        #pragma unroll
        for (int i = 0; i < 4; i++) oa[nt][i] = 0.f;
    float m0 = -1e30f, m1 = -1e30f, l0 = 0.f, l1 = 0.f;

    const uint32_t sKs = (uint32_t)__cvta_generic_to_shared(Ks);
    const uint32_t sVs = (uint32_t)__cvta_generic_to_shared(Vs);

    const int ktmax = 2 * qt + 1;

    // prologue: stage 0 into buffer 0
    {
        const float* kg = kg0;
        const float* vg = vg0;
        #pragma unroll
        for (int i = 0; i < 4; i++) {
            const int idx = tid + i * 256;
            const int r = idx >> 4;
            const int c = (idx & 15) << 2;
            cp16(sKs + (uint32_t)(r * AT_KS + c) * 4, kg + (size_t)r * QS + c);
            cp16(sVs + (uint32_t)(r * AT_VS + c) * 4, vg + (size_t)r * QS + c);
        }
        asm volatile("cp.async.commit_group;");
    }

    for (int kt = 0; kt <= ktmax; kt++) {
        const int cur = kt & 1;
        asm volatile("cp.async.wait_group 0;");
        __syncthreads();   // stage kt visible; all warps done with iter kt-1 (frees buf cur^1)

        if (kt < ktmax) {
            const int nxt = cur ^ 1;
            const float* kg = kg0 + (size_t)((kt + 1) * 64) * QS;
            const float* vg = vg0 + (size_t)((kt + 1) * 64) * QS;
            const uint32_t ko = (uint32_t)(nxt * KSTG) * 4;
            const uint32_t vo = (uint32_t)(nxt * VSTG) * 4;
            #pragma unroll
            for (int i = 0; i < 4; i++) {
                const int idx = tid + i * 256;
                const int r = idx >> 4;
                const int c = (idx & 15) << 2;
                cp16(sKs + ko + (uint32_t)(r * AT_KS + c) * 4, kg + (size_t)r * QS + c);
                cp16(sVs + vo + (uint32_t)(r * AT_VS + c) * 4, vg + (size_t)r * QS + c);
            }
            asm volatile("cp.async.commit_group;");
        } else {
            asm volatile("cp.async.commit_group;");
        }

        const float* ks = Ks + cur * KSTG;
        const float* vs = Vs + cur * VSTG;

        float s[8][4];
        #pragma unroll
        for (int nt = 0; nt < 8; nt++)
            #pragma unroll
            for (int i = 0; i < 4; i++) s[nt][i] = 0.f;

        #pragma unroll
        for (int kd = 0; kd < 8; kd++) {
            #pragma unroll
            for (int nt = 0; nt < 8; nt++) {
                uint32_t bf[2];
                const float* p = &ks[(nt * 8 + g) * AT_KS + kd * 8 + t4];
                bf[0] = __float_as_uint(p[0]);
                bf[1] = __float_as_uint(p[4]);
                mma_tf32(s[nt], qf[kd], bf);
            }
        }

        const int key0 = kt * 64;
        const bool need_mask = (kt >= 2 * qt);
        #pragma unroll
        for (int nt = 0; nt < 8; nt++) {
            const int c0 = key0 + nt * 8 + 2 * t4;
            const int c1 = c0 + 1;
            s[nt][0] = s[nt][0] * 0.125f + 0.01f * (float)c0;
            s[nt][1] = s[nt][1] * 0.125f + 0.01f * (float)c1;
            s[nt][2] = s[nt][2] * 0.125f + 0.01f * (float)c0;
            s[nt][3] = s[nt][3] * 0.125f + 0.01f * (float)c1;
            if (need_mask) {
                if (c0 > grow0) s[nt][0] = -1e30f;
                if (c1 > grow0) s[nt][1] = -1e30f;
                if (c0 > grow1) s[nt][2] = -1e30f;
                if (c1 > grow1) s[nt][3] = -1e30f;
            }
        }

        float mx0 = -1e30f, mx1 = -1e30f;
        #pragma unroll
        for (int nt = 0; nt < 8; nt++) {
            mx0 = fmaxf(mx0, fmaxf(s[nt][0], s[nt][1]));
            mx1 = fmaxf(mx1, fmaxf(s[nt][2], s[nt][3]));
        }
        mx0 = fmaxf(mx0, __shfl_xor_sync(0xffffffffu, mx0, 1));
        mx0 = fmaxf(mx0, __shfl_xor_sync(0xffffffffu, mx0, 2));
        mx1 = fmaxf(mx1, __shfl_xor_sync(0xffffffffu, mx1, 1));
        mx1 = fmaxf(mx1, __shfl_xor_sync(0xffffffffu, mx1, 2));
        const float mn0 = fmaxf(m0, mx0);
        const float mn1 = fmaxf(m1, mx1);

        float sum0 = 0.f, sum1 = 0.f;
        #pragma unroll
        for (int nt = 0; nt < 8; nt++) {
            s[nt][0] = __expf(s[nt][0] - mn0);
            s[nt][1] = __expf(s[nt][1] - mn0);
            s[nt][2] = __expf(s[nt][2] - mn1);
            s[nt][3] = __expf(s[nt][3] - mn1);
            sum0 += s[nt][0] + s[nt][1];
            sum1 += s[nt][2] + s[nt][3];
        }
        sum0 += __shfl_xor_sync(0xffffffffu, sum0, 1);
        sum0 += __shfl_xor_sync(0xffffffffu, sum0, 2);
        sum1 += __shfl_xor_sync(0xffffffffu, sum1, 1);
        sum1 += __shfl_xor_sync(0xffffffffu, sum1, 2);

        const float corr0 = __expf(m0 - mn0);
        const float corr1 = __expf(m1 - mn1);
        l0 = l0 * corr0 + sum0;
        l1 = l1 * corr1 + sum1;
        m0 = mn0; m1 = mn1;
        #pragma unroll
        for (int nt = 0; nt < 8; nt++) {
            oa[nt][0] *= corr0; oa[nt][1] *= corr0;
            oa[nt][2] *= corr1; oa[nt][3] *= corr1;
        }

        {
            const int pr0 = warp * 16 + g;
            #pragma unroll
            for (int nt = 0; nt < 8; nt++) {
                const int c = nt * 8 + 2 * t4;
                *reinterpret_cast<float2*>(&Ps[pr0 * AT_PS + c])       = make_float2(s[nt][0], s[nt][1]);
                *reinterpret_cast<float2*>(&Ps[(pr0 + 8) * AT_PS + c]) = make_float2(s[nt][2], s[nt][3]);
            }
        }
        __syncthreads();

        const int pr0 = warp * 16 + g;
        #pragma unroll
        for (int kd = 0; kd < 8; kd++) {
            uint32_t pa[4];
            pa[0] = __float_as_uint(Ps[pr0 * AT_PS + kd * 8 + t4]);
            pa[1] = __float_as_uint(Ps[(pr0 + 8) * AT_PS + kd * 8 + t4]);
            pa[2] = __float_as_uint(Ps[pr0 * AT_PS + kd * 8 + t4 + 4]);
            pa[3] = __float_as_uint(Ps[(pr0 + 8) * AT_PS + kd * 8 + t4 + 4]);
            #pragma unroll
            for (int nt = 0; nt < 8; nt++) {
                uint32_t bf[2];
                bf[0] = __float_as_uint(vs[(kd * 8 + t4) * AT_VS + nt * 8 + g]);
                bf[1] = __float_as_uint(vs[(kd * 8 + t4 + 4) * AT_VS + nt * 8 + g]);
                mma_tf32(oa[nt], pa, bf);
            }
        }
    }

    const float inv0 = 1.f / l0;
    const float inv1 = 1.f / l1;
    float* og = O + (size_t)b * LL * DD + (size_t)h * HDIM;
    #pragma unroll
    for (int nt = 0; nt < 8; nt++) {
        const int c = nt * 8 + 2 * t4;
        *reinterpret_cast<float2*>(&og[(size_t)grow0 * DD + c]) =
            make_float2(tf32r(oa[nt][0] * inv0), tf32r(oa[nt][1] * inv0));
        *reinterpret_cast<float2*>(&og[(size_t)grow1 * DD + c]) =
            make_float2(tf32r(oa[nt][2] * inv1), tf32r(oa[nt][3] * inv1));
    }
}

// ---------------- launch ----------------
extern "C" void kernel_launch(void* const* d_in, const int* in_sizes, int n_in,
                              void* d_out, int out_size)
{
    const float* x    = (const float*)d_in[0];
    const float* wq   = (const float*)d_in[2];
    const float* wk   = (const float*)d_in[3];
    const float* wv   = (const float*)d_in[4];
    const float* wo   = (const float*)d_in[5];
    const float* ln1g = (const float*)d_in[6];
    const float* ln1b = (const float*)d_in[7];
    const float* ln2g = (const float*)d_in[8];
    const float* ln2b = (const float*)d_in[9];
    const float* w1   = (const float*)d_in[10];
    const float* b1   = (const float*)d_in[11];
    const float* wg   = (const float*)d_in[12];
    const float* w2   = (const float*)d_in[13];
    const float* b2   = (const float*)d_in[14];
    float* out = (float*)d_out;

    float *p_ln1, *p_qkv, *p_attn, *p_h, *p_ln2, *p_f, *p_wb;
    cudaGetSymbolAddress((void**)&p_ln1,  g_ln1);
    cudaGetSymbolAddress((void**)&p_qkv,  g_qkv);
    cudaGetSymbolAddress((void**)&p_attn, g_attn);
    cudaGetSymbolAddress((void**)&p_h,    g_h);
    cudaGetSymbolAddress((void**)&p_ln2,  g_ln2);
    cudaGetSymbolAddress((void**)&p_f,    g_f);
    cudaGetSymbolAddress((void**)&p_wb,   g_wbuf);

    float* rwqkv = p_wb;                               // [3072,1024]
    float* rwo   = p_wb + (size_t)3*1024*1024;         // [1024,1024]
    float* rw1g  = p_wb + (size_t)4*1024*1024;         // [8192,1024] interleaved
    float* rw2   = p_wb + (size_t)12*1024*1024;        // [1024,4096]

    cudaFuncSetAttribute(mma_gemm_nt, cudaFuncAttributeMaxDynamicSharedMemorySize,
                         GEMM_SMEM_BYTES);
    cudaFuncSetAttribute(attn_mma, cudaFuncAttributeMaxDynamicSharedMemorySize,
                         ATTN_SMEM_BYTES);

    // 0) weight prep (tf32-RN; w1/wg row-interleaved)
    const int n4_d = DD*DD/4;
    const int n4_h = HIDD*DD/4;
    round_w<<<(n4_d+255)/256, 256>>>(wq, rwqkv,                 n4_d);
    round_w<<<(n4_d+255)/256, 256>>>(wk, rwqkv + (size_t)DD*DD, n4_d);
    round_w<<<(n4_d+255)/256, 256>>>(wv, rwqkv + (size_t)2*DD*DD, n4_d);
    round_w<<<(n4_d+255)/256, 256>>>(wo, rwo, n4_d);
    round_interleave<<<(n4_h+255)/256, 256>>>(w1, wg, rw1g);
    round_w<<<(n4_h+255)/256, 256>>>(w2, rw2, n4_h);

    // 1) ln1
    ln_kernel<<<NROWS, 256>>>(x, ln1g, ln1b, p_ln1);

    // 2) fused QKV projection: [4096,3072] = ln1 @ [wq;wk;wv]^T
    dim3 gQKV(QS / 128, NROWS / 128);
    mma_gemm_nt<<<gQKV, 256, GEMM_SMEM_BYTES>>>(p_ln1, rwqkv, p_qkv, NROWS, QS, DD,
                                                nullptr, nullptr, EP_ROUND);

    // 3) causal flash attention (packed qkv)
    dim3 gAttn(LL / 128, BB * HH);
    attn_mma<<<gAttn, 256, ATTN_SMEM_BYTES>>>(p_qkv, p_attn);

    // 4) output projection + residual -> h
    dim3 gO(DD / 128, NROWS / 128);
    mma_gemm_nt<<<gO, 256, GEMM_SMEM_BYTES>>>(p_attn, rwo, p_h, NROWS, DD, DD,
                                              nullptr, x, EP_RES);

    // 5) ln2
    ln_kernel<<<NROWS, 256>>>(p_h, ln2g, ln2b, p_ln2);

    // 6) fused FFN up+gate: f = silu(ln2@w1^T + b1) * (ln2@wg^T)
    dim3 gF(8192 / 128, NROWS / 128);
    mma_gemm_nt<<<gF, 256, GEMM_SMEM_BYTES>>>(p_ln2, rw1g, p_f, NROWS, 8192, DD,
                                              b1, nullptr, EP_SILU_PAIR);

    // 7) out = f @ w2^T + b2 + h
    mma_gemm_nt<<<gO, 256, GEMM_SMEM_BYTES>>>(p_f, rw2, out, NROWS, DD, HIDD,
                                              b2, p_h, EP_BIAS_RES);
}